// round 8
// baseline (speedup 1.0000x reference)
#include <cuda_runtime.h>
#include <math.h>

// ---------------------------------------------------------------------------
// Problem constants
//   B=16, H=W=64, DIM=256, HEADS=8, DHEAD=32, WS=8, SHIFT=4
//   N=64 tokens/window, NW=64 windows/image, NWIN=1024 total windows
//   NTOK = B*H*W = 65536 tokens
// ---------------------------------------------------------------------------
#define NTOK 65536
#define DIMC 256
#define SCALE_Q 0.17677669529663687f   // 32^-0.5

// ---------------------------------------------------------------------------
// Scratch (device globals — no allocations allowed)
// ---------------------------------------------------------------------------
__device__ float g_x0w[(size_t)NTOK * DIMC];        // LN(x0), rolled+windowed
__device__ float g_x1w[(size_t)NTOK * DIMC];        // LN(x1), rolled+windowed
__device__ float g_q  [(size_t)NTOK * DIMC];        // scaled Q
__device__ float g_kv [(size_t)NTOK * 2 * DIMC];    // [K(256) | V(256)]
__device__ float g_o  [(size_t)NTOK * DIMC];        // attention output (windowed order)
__device__ float g_x  [(size_t)NTOK * DIMC];        // x = shortcut + attn (token order)
__device__ float g_xn [(size_t)NTOK * DIMC];        // LN2(x)
__device__ float g_h  [(size_t)NTOK * 1024];        // gelu(fc1)

__device__ __forceinline__ float* buf(int id) {
    switch (id) {
        case 0: return g_x0w;
        case 1: return g_x1w;
        case 2: return g_q;
        case 3: return g_kv;
        case 4: return g_o;
        case 5: return g_x;
        case 6: return g_xn;
        default: return g_h;
    }
}

// windowed row index (w*64+t) -> flat token index (b*4096 + h*64 + w)
// Accounts for the cyclic shift by -4 on both axes (same map used for the
// gather before attention and the scatter after: roll(-s) gather == roll(+s) scatter).
__device__ __forceinline__ int win_to_flat(int m) {
    int w  = m >> 6, t = m & 63;
    int b  = w >> 6, wi = w & 63;
    int hs = ((wi >> 3) << 3) + (t >> 3);
    int ws = ((wi & 7) << 3) + (t & 7);
    int hh = (hs + 4) & 63;
    int ww = (ws + 4) & 63;
    return (b << 12) + (hh << 6) + ww;
}

// ---------------------------------------------------------------------------
// Kernel 1: LN(x0), LN(x1) + roll + window partition.  One warp per token.
// grid = 16384 blocks * 256 thr = 131072 warps = 2 * 65536 tokens.
// ---------------------------------------------------------------------------
__global__ __launch_bounds__(256) void ln_win_k(
    const float* __restrict__ x0, const float* __restrict__ x1,
    const float* __restrict__ g0, const float* __restrict__ b0,
    const float* __restrict__ g1, const float* __restrict__ b1)
{
    int warp = blockIdx.x * 8 + (threadIdx.x >> 5);
    int lane = threadIdx.x & 31;
    int which = warp >> 16;           // 0 -> x0, 1 -> x1
    int tok   = warp & (NTOK - 1);    // windowed row index
    int flat  = win_to_flat(tok);

    const float* src = which ? x1 : x0;
    const float* gg  = which ? g1 : g0;
    const float* bb  = which ? b1 : b0;
    float* dst       = which ? g_x1w : g_x0w;

    const float4* p = (const float4*)(src + (size_t)flat * DIMC);
    float4 u = p[lane * 2], v = p[lane * 2 + 1];

    float s = u.x + u.y + u.z + u.w + v.x + v.y + v.z + v.w;
    float q = u.x*u.x + u.y*u.y + u.z*u.z + u.w*u.w
            + v.x*v.x + v.y*v.y + v.z*v.z + v.w*v.w;
    #pragma unroll
    for (int o = 16; o; o >>= 1) {
        s += __shfl_xor_sync(0xffffffffu, s, o);
        q += __shfl_xor_sync(0xffffffffu, q, o);
    }
    float mean = s * (1.0f / 256.0f);
    float var  = q * (1.0f / 256.0f) - mean * mean;
    float rstd = rsqrtf(var + 1e-5f);

    const float4* gp = (const float4*)gg;
    const float4* bp = (const float4*)bb;
    float4 gu = gp[lane * 2], gv = gp[lane * 2 + 1];
    float4 bu = bp[lane * 2], bv = bp[lane * 2 + 1];

    float4 ou, ov;
    ou.x = (u.x - mean) * rstd * gu.x + bu.x;
    ou.y = (u.y - mean) * rstd * gu.y + bu.y;
    ou.z = (u.z - mean) * rstd * gu.z + bu.z;
    ou.w = (u.w - mean) * rstd * gu.w + bu.w;
    ov.x = (v.x - mean) * rstd * gv.x + bv.x;
    ov.y = (v.y - mean) * rstd * gv.y + bv.y;
    ov.z = (v.z - mean) * rstd * gv.z + bv.z;
    ov.w = (v.w - mean) * rstd * gv.w + bv.w;

    float4* op = (float4*)(dst + (size_t)tok * DIMC);
    op[lane * 2]     = ou;
    op[lane * 2 + 1] = ov;
}

// ---------------------------------------------------------------------------
// Kernel: LN2 of g_x -> g_xn (token order, no remap)
// ---------------------------------------------------------------------------
__global__ __launch_bounds__(256) void ln2_k(
    const float* __restrict__ gg, const float* __restrict__ bb)
{
    int warp = blockIdx.x * 8 + (threadIdx.x >> 5);
    int lane = threadIdx.x & 31;

    const float4* p = (const float4*)(g_x + (size_t)warp * DIMC);
    float4 u = p[lane * 2], v = p[lane * 2 + 1];

    float s = u.x + u.y + u.z + u.w + v.x + v.y + v.z + v.w;
    float q = u.x*u.x + u.y*u.y + u.z*u.z + u.w*u.w
            + v.x*v.x + v.y*v.y + v.z*v.z + v.w*v.w;
    #pragma unroll
    for (int o = 16; o; o >>= 1) {
        s += __shfl_xor_sync(0xffffffffu, s, o);
        q += __shfl_xor_sync(0xffffffffu, q, o);
    }
    float mean = s * (1.0f / 256.0f);
    float var  = q * (1.0f / 256.0f) - mean * mean;
    float rstd = rsqrtf(var + 1e-5f);

    const float4* gp = (const float4*)gg;
    const float4* bp = (const float4*)bb;
    float4 gu = gp[lane * 2], gv = gp[lane * 2 + 1];
    float4 bu = bp[lane * 2], bv = bp[lane * 2 + 1];

    float4 ou, ov;
    ou.x = (u.x - mean) * rstd * gu.x + bu.x;
    ou.y = (u.y - mean) * rstd * gu.y + bu.y;
    ou.z = (u.z - mean) * rstd * gu.z + bu.z;
    ou.w = (u.w - mean) * rstd * gu.w + bu.w;
    ov.x = (v.x - mean) * rstd * gv.x + bv.x;
    ov.y = (v.y - mean) * rstd * gv.y + bv.y;
    ov.z = (v.z - mean) * rstd * gv.z + bv.z;
    ov.w = (v.w - mean) * rstd * gv.w + bv.w;

    float4* op = (float4*)(g_xn + (size_t)warp * DIMC);
    op[lane * 2]     = ou;
    op[lane * 2 + 1] = ov;
}

// ---------------------------------------------------------------------------
// Generic SGEMM: C[m,n] = sum_k A[m,k] * W[n,k]  (+epilogue)
// A: M x K row-major (M = 65536 via gridDim.y*128), W: N x K row-major.
// 128x128x16 tiles, 256 threads, 8x8 per thread.
// ---------------------------------------------------------------------------
#define EPI_SCALE   0   // C = (acc + bias) * scale
#define EPI_BIAS    1   // C = acc + bias
#define EPI_GELU    2   // C = gelu_exact(acc + bias)
#define EPI_SCATTER 3   // C[map(m)] = acc + bias + R[map(m)]
#define EPI_RESID   4   // C = acc + bias + R[m]

template<int EPI>
__global__ __launch_bounds__(256) void gemm_k(
    int a_id, const float* __restrict__ W, const float* __restrict__ bias,
    int r_id, const float* __restrict__ r_ext,
    int c_id, float* __restrict__ c_ext,
    int N, int K, float scale)
{
    const float* A = buf(a_id);
    float* C = (c_id >= 0) ? buf(c_id) : c_ext;
    const float* R = nullptr;
    if (EPI == EPI_SCATTER || EPI == EPI_RESID)
        R = (r_id >= 0) ? buf(r_id) : r_ext;

    __shared__ float As[16][132];
    __shared__ float Bs[16][132];

    int tid = threadIdx.x;
    int m0 = blockIdx.y * 128, n0 = blockIdx.x * 128;
    int lr = tid >> 2;
    int lc = (tid & 3) << 2;
    int tx = tid & 15, ty = tid >> 4;

    const float* Ap = A + (size_t)(m0 + lr) * K + lc;
    const float* Wp = W + (size_t)(n0 + lr) * K + lc;

    float acc[8][8];
    #pragma unroll
    for (int i = 0; i < 8; i++)
        #pragma unroll
        for (int j = 0; j < 8; j++) acc[i][j] = 0.0f;

    for (int kt = 0; kt < K; kt += 16) {
        float4 a0 = *(const float4*)Ap;
        float4 a1 = *(const float4*)(Ap + (size_t)64 * K);
        float4 w0 = *(const float4*)Wp;
        float4 w1 = *(const float4*)(Wp + (size_t)64 * K);
        __syncthreads();
        As[lc + 0][lr] = a0.x; As[lc + 1][lr] = a0.y;
        As[lc + 2][lr] = a0.z; As[lc + 3][lr] = a0.w;
        As[lc + 0][lr + 64] = a1.x; As[lc + 1][lr + 64] = a1.y;
        As[lc + 2][lr + 64] = a1.z; As[lc + 3][lr + 64] = a1.w;
        Bs[lc + 0][lr] = w0.x; Bs[lc + 1][lr] = w0.y;
        Bs[lc + 2][lr] = w0.z; Bs[lc + 3][lr] = w0.w;
        Bs[lc + 0][lr + 64] = w1.x; Bs[lc + 1][lr + 64] = w1.y;
        Bs[lc + 2][lr + 64] = w1.z; Bs[lc + 3][lr + 64] = w1.w;
        __syncthreads();
        Ap += 16; Wp += 16;

        #pragma unroll
        for (int k = 0; k < 16; k++) {
            float4 av0 = *(const float4*)&As[k][ty * 8];
            float4 av1 = *(const float4*)&As[k][ty * 8 + 4];
            float4 bv0 = *(const float4*)&Bs[k][tx * 8];
            float4 bv1 = *(const float4*)&Bs[k][tx * 8 + 4];
            float a[8] = {av0.x, av0.y, av0.z, av0.w, av1.x, av1.y, av1.z, av1.w};
            float b[8] = {bv0.x, bv0.y, bv0.z, bv0.w, bv1.x, bv1.y, bv1.z, bv1.w};
            #pragma unroll
            for (int i = 0; i < 8; i++)
                #pragma unroll
                for (int j = 0; j < 8; j++)
                    acc[i][j] = fmaf(a[i], b[j], acc[i][j]);
        }
    }

    int col = n0 + tx * 8;
    float bl[8];
    #pragma unroll
    for (int j = 0; j < 8; j++) bl[j] = bias[col + j];

    #pragma unroll
    for (int i = 0; i < 8; i++) {
        int row = m0 + ty * 8 + i;
        size_t crow;
        if (EPI == EPI_SCATTER) crow = (size_t)win_to_flat(row) * N;
        else                    crow = (size_t)row * N;

        float o[8];
        #pragma unroll
        for (int j = 0; j < 8; j++) {
            float v = acc[i][j] + bl[j];
            if (EPI == EPI_SCALE) v *= scale;
            if (EPI == EPI_GELU)  v = 0.5f * v * (1.0f + erff(v * 0.70710678118654752f));
            o[j] = v;
        }
        if (EPI == EPI_SCATTER || EPI == EPI_RESID) {
            float4 r0 = *(const float4*)&R[crow + col];
            float4 r1 = *(const float4*)&R[crow + col + 4];
            o[0] += r0.x; o[1] += r0.y; o[2] += r0.z; o[3] += r0.w;
            o[4] += r1.x; o[5] += r1.y; o[6] += r1.z; o[7] += r1.w;
        }
        *(float4*)&C[crow + col]     = make_float4(o[0], o[1], o[2], o[3]);
        *(float4*)&C[crow + col + 4] = make_float4(o[4], o[5], o[6], o[7]);
    }
}

// ---------------------------------------------------------------------------
// Attention: one block per (head, window). S = Q K^T + rpb + shiftmask,
// softmax, O = P V.  Q pre-scaled.  N=64, DHEAD=32.
// ---------------------------------------------------------------------------
__global__ __launch_bounds__(256) void attn_k(const float* __restrict__ rpb)
{
    __shared__ float Qs[64][33];
    __shared__ float Ks[64][33];
    __shared__ float Vs[64][33];
    __shared__ float S[64][65];
    __shared__ int   lab[64];

    int h = blockIdx.x;    // 0..7
    int w = blockIdx.y;    // 0..1023
    int tid = threadIdx.x;

    int t  = tid >> 2;
    int d0 = (tid & 3) << 3;
    {
        const float* qp = g_q + ((size_t)(w * 64 + t) * 256 + h * 32 + d0);
        float4 a = *(const float4*)qp, b = *(const float4*)(qp + 4);
        Qs[t][d0 + 0] = a.x; Qs[t][d0 + 1] = a.y; Qs[t][d0 + 2] = a.z; Qs[t][d0 + 3] = a.w;
        Qs[t][d0 + 4] = b.x; Qs[t][d0 + 5] = b.y; Qs[t][d0 + 6] = b.z; Qs[t][d0 + 7] = b.w;
        const float* kp = g_kv + ((size_t)(w * 64 + t) * 512 + h * 32 + d0);
        float4 ka = *(const float4*)kp, kb = *(const float4*)(kp + 4);
        Ks[t][d0 + 0] = ka.x; Ks[t][d0 + 1] = ka.y; Ks[t][d0 + 2] = ka.z; Ks[t][d0 + 3] = ka.w;
        Ks[t][d0 + 4] = kb.x; Ks[t][d0 + 5] = kb.y; Ks[t][d0 + 6] = kb.z; Ks[t][d0 + 7] = kb.w;
        const float* vp = kp + 256;
        float4 va = *(const float4*)vp, vb = *(const float4*)(vp + 4);
        Vs[t][d0 + 0] = va.x; Vs[t][d0 + 1] = va.y; Vs[t][d0 + 2] = va.z; Vs[t][d0 + 3] = va.w;
        Vs[t][d0 + 4] = vb.x; Vs[t][d0 + 5] = vb.y; Vs[t][d0 + 6] = vb.z; Vs[t][d0 + 7] = vb.w;
    }
    if (tid < 64) {
        int wi = w & 63, wr = wi >> 3, wc = wi & 7;
        int rr = tid >> 3, cc = tid & 7;
        int lh = (wr < 7) ? 0 : ((rr < 4) ? 1 : 2);
        int lw = (wc < 7) ? 0 : ((cc < 4) ? 1 : 2);
        lab[tid] = lh * 3 + lw;
    }
    __syncthreads();

    // S = Q K^T + bias + mask: thread computes row r, 16 cols
    int r  = tid >> 2;
    int j0 = (tid & 3) << 4;
    int ri = r >> 3, ci = r & 7;
    float qreg[32];
    #pragma unroll
    for (int k = 0; k < 32; k++) qreg[k] = Qs[r][k];
    int lr_ = lab[r];

    for (int jj = 0; jj < 16; jj++) {
        int j = j0 + jj;
        float s = 0.0f;
        #pragma unroll
        for (int k = 0; k < 32; k++) s = fmaf(qreg[k], Ks[j][k], s);
        int rj = j >> 3, cj = j & 7;
        int idx = (ri - rj + 7) * 15 + (ci - cj + 7);
        s += rpb[idx * 8 + h];
        if (lr_ != lab[j]) s -= 100.0f;
        S[r][j] = s;
    }
    __syncthreads();

    // softmax per row (64 rows, one thread each)
    if (tid < 64) {
        float m = -1e30f;
        for (int j = 0; j < 64; j++) m = fmaxf(m, S[tid][j]);
        float sum = 0.0f;
        for (int j = 0; j < 64; j++) {
            float e = expf(S[tid][j] - m);
            S[tid][j] = e;
            sum += e;
        }
        float inv = 1.0f / sum;
        for (int j = 0; j < 64; j++) S[tid][j] *= inv;
    }
    __syncthreads();

    // O = P V: thread computes row r, 8 dhead cols
    float o8[8] = {0, 0, 0, 0, 0, 0, 0, 0};
    #pragma unroll
    for (int j = 0; j < 64; j++) {
        float p = S[r][j];
        #pragma unroll
        for (int dd = 0; dd < 8; dd++) o8[dd] = fmaf(p, Vs[j][d0 + dd], o8[dd]);
    }
    float* op = g_o + ((size_t)(w * 64 + r) * 256 + h * 32 + d0);
    *(float4*)op       = make_float4(o8[0], o8[1], o8[2], o8[3]);
    *(float4*)(op + 4) = make_float4(o8[4], o8[5], o8[6], o8[7]);
}

// ---------------------------------------------------------------------------
// launch
// ---------------------------------------------------------------------------
extern "C" void kernel_launch(void* const* d_in, const int* in_sizes, int n_in,
                              void* d_out, int out_size)
{
    const float* x0   = (const float*)d_in[0];
    const float* x1   = (const float*)d_in[1];
    const float* g1_0 = (const float*)d_in[2];
    const float* b1_0 = (const float*)d_in[3];
    const float* g1_1 = (const float*)d_in[4];
    const float* b1_1 = (const float*)d_in[5];
    const float* Wq   = (const float*)d_in[6];
    const float* bq   = (const float*)d_in[7];
    const float* Wkv  = (const float*)d_in[8];
    const float* bkv  = (const float*)d_in[9];
    const float* rpb  = (const float*)d_in[10];
    const float* Wp   = (const float*)d_in[11];
    const float* bp   = (const float*)d_in[12];
    const float* g2   = (const float*)d_in[13];
    const float* b2   = (const float*)d_in[14];
    const float* Wfc1 = (const float*)d_in[15];
    const float* bfc1 = (const float*)d_in[16];
    const float* Wfc2 = (const float*)d_in[17];
    const float* bfc2 = (const float*)d_in[18];
    float* out = (float*)d_out;

    // 1) LN(x0), LN(x1) + shift + window partition -> g_x0w (id 0), g_x1w (id 1)
    ln_win_k<<<16384, 256>>>(x0, x1, g1_0, b1_0, g1_1, b1_1);

    // 2) Q = (x1w @ Wq^T + bq) * scale -> g_q (id 2)
    gemm_k<EPI_SCALE><<<dim3(2, 512), 256>>>(1, Wq, bq, -1, nullptr, 2, nullptr,
                                             256, 256, SCALE_Q);
    // 3) KV = x0w @ Wkv^T + bkv -> g_kv (id 3)
    gemm_k<EPI_BIAS><<<dim3(4, 512), 256>>>(0, Wkv, bkv, -1, nullptr, 3, nullptr,
                                            512, 256, 1.0f);
    // 4) attention -> g_o (id 4)
    attn_k<<<dim3(8, 1024), 256>>>(rpb);

    // 5) x = x1 + scatter(attn_out @ Wp^T + bp) -> g_x (id 5)
    gemm_k<EPI_SCATTER><<<dim3(2, 512), 256>>>(4, Wp, bp, -1, x1, 5, nullptr,
                                               256, 256, 1.0f);
    // 6) xn = LN2(x) -> g_xn (id 6)
    ln2_k<<<8192, 256>>>(g2, b2);

    // 7) h = gelu(xn @ Wfc1^T + bfc1) -> g_h (id 7)
    gemm_k<EPI_GELU><<<dim3(8, 512), 256>>>(6, Wfc1, bfc1, -1, nullptr, 7, nullptr,
                                            1024, 256, 1.0f);
    // 8) out = x + h @ Wfc2^T + bfc2 -> d_out
    gemm_k<EPI_RESID><<<dim3(2, 512), 256>>>(7, Wfc2, bfc2, 5, nullptr, -1, out,
                                             256, 1024, 1.0f);
}

// round 9
// speedup vs baseline: 2.3665x; 2.3665x over previous
#include <cuda_runtime.h>
#include <math.h>
#include <stdint.h>

// ---------------------------------------------------------------------------
// Problem constants
//   B=16, H=W=64, DIM=256, HEADS=8, DHEAD=32, WS=8, SHIFT=4
//   N=64 tokens/window, NW=64 windows/image, NWIN=1024 total windows
//   NTOK = B*H*W = 65536 tokens
// ---------------------------------------------------------------------------
#define NTOK 65536
#define DIMC 256
#define SCALE_Q 0.17677669529663687f   // 32^-0.5

// ---------------------------------------------------------------------------
// Scratch (device globals — no allocations allowed)
// ---------------------------------------------------------------------------
__device__ float g_x0w[(size_t)NTOK * DIMC];        // LN(x0), rolled+windowed
__device__ float g_x1w[(size_t)NTOK * DIMC];        // LN(x1), rolled+windowed
__device__ float g_q  [(size_t)NTOK * DIMC];        // scaled Q
__device__ float g_kv [(size_t)NTOK * 2 * DIMC];    // [K(256) | V(256)]
__device__ float g_o  [(size_t)NTOK * DIMC];        // attention output (windowed order)
__device__ float g_x  [(size_t)NTOK * DIMC];        // x = shortcut + attn (token order)
__device__ float g_xn [(size_t)NTOK * DIMC];        // LN2(x)
__device__ float g_h  [(size_t)NTOK * 1024];        // gelu(fc1)

__device__ __forceinline__ float* buf(int id) {
    switch (id) {
        case 0: return g_x0w;
        case 1: return g_x1w;
        case 2: return g_q;
        case 3: return g_kv;
        case 4: return g_o;
        case 5: return g_x;
        case 6: return g_xn;
        default: return g_h;
    }
}

// windowed row index (w*64+t) -> flat token index (b*4096 + h*64 + w)
__device__ __forceinline__ int win_to_flat(int m) {
    int w  = m >> 6, t = m & 63;
    int b  = w >> 6, wi = w & 63;
    int hs = ((wi >> 3) << 3) + (t >> 3);
    int ws = ((wi & 7) << 3) + (t & 7);
    int hh = (hs + 4) & 63;
    int ww = (ws + 4) & 63;
    return (b << 12) + (hh << 6) + ww;
}

// fp32 -> tf32 with round-to-nearest (zero-mean error; truncation would bias)
__device__ __forceinline__ uint32_t f2tf(float x) {
    uint32_t r;
    asm("cvt.rna.tf32.f32 %0, %1;" : "=r"(r) : "f"(x));
    return r;
}

__device__ __forceinline__ void mma_tf32(float c[4], const uint32_t a[4],
                                         uint32_t b0, uint32_t b1) {
    asm volatile(
        "mma.sync.aligned.m16n8k8.row.col.f32.tf32.tf32.f32 "
        "{%0,%1,%2,%3}, {%4,%5,%6,%7}, {%8,%9}, {%0,%1,%2,%3};\n"
        : "+f"(c[0]), "+f"(c[1]), "+f"(c[2]), "+f"(c[3])
        : "r"(a[0]), "r"(a[1]), "r"(a[2]), "r"(a[3]), "r"(b0), "r"(b1));
}

// ---------------------------------------------------------------------------
// Kernel 1: LN(x0), LN(x1) + roll + window partition.  One warp per token.
// ---------------------------------------------------------------------------
__global__ __launch_bounds__(256) void ln_win_k(
    const float* __restrict__ x0, const float* __restrict__ x1,
    const float* __restrict__ g0, const float* __restrict__ b0,
    const float* __restrict__ g1, const float* __restrict__ b1)
{
    int warp = blockIdx.x * 8 + (threadIdx.x >> 5);
    int lane = threadIdx.x & 31;
    int which = warp >> 16;
    int tok   = warp & (NTOK - 1);
    int flat  = win_to_flat(tok);

    const float* src = which ? x1 : x0;
    const float* gg  = which ? g1 : g0;
    const float* bb  = which ? b1 : b0;
    float* dst       = which ? g_x1w : g_x0w;

    const float4* p = (const float4*)(src + (size_t)flat * DIMC);
    float4 u = p[lane * 2], v = p[lane * 2 + 1];

    float s = u.x + u.y + u.z + u.w + v.x + v.y + v.z + v.w;
    float q = u.x*u.x + u.y*u.y + u.z*u.z + u.w*u.w
            + v.x*v.x + v.y*v.y + v.z*v.z + v.w*v.w;
    #pragma unroll
    for (int o = 16; o; o >>= 1) {
        s += __shfl_xor_sync(0xffffffffu, s, o);
        q += __shfl_xor_sync(0xffffffffu, q, o);
    }
    float mean = s * (1.0f / 256.0f);
    float var  = q * (1.0f / 256.0f) - mean * mean;
    float rstd = rsqrtf(var + 1e-5f);

    const float4* gp = (const float4*)gg;
    const float4* bp = (const float4*)bb;
    float4 gu = gp[lane * 2], gv = gp[lane * 2 + 1];
    float4 bu = bp[lane * 2], bv = bp[lane * 2 + 1];

    float4 ou, ov;
    ou.x = (u.x - mean) * rstd * gu.x + bu.x;
    ou.y = (u.y - mean) * rstd * gu.y + bu.y;
    ou.z = (u.z - mean) * rstd * gu.z + bu.z;
    ou.w = (u.w - mean) * rstd * gu.w + bu.w;
    ov.x = (v.x - mean) * rstd * gv.x + bv.x;
    ov.y = (v.y - mean) * rstd * gv.y + bv.y;
    ov.z = (v.z - mean) * rstd * gv.z + bv.z;
    ov.w = (v.w - mean) * rstd * gv.w + bv.w;

    float4* op = (float4*)(dst + (size_t)tok * DIMC);
    op[lane * 2]     = ou;
    op[lane * 2 + 1] = ov;
}

// ---------------------------------------------------------------------------
// Kernel: LN2 of g_x -> g_xn (token order)
// ---------------------------------------------------------------------------
__global__ __launch_bounds__(256) void ln2_k(
    const float* __restrict__ gg, const float* __restrict__ bb)
{
    int warp = blockIdx.x * 8 + (threadIdx.x >> 5);
    int lane = threadIdx.x & 31;

    const float4* p = (const float4*)(g_x + (size_t)warp * DIMC);
    float4 u = p[lane * 2], v = p[lane * 2 + 1];

    float s = u.x + u.y + u.z + u.w + v.x + v.y + v.z + v.w;
    float q = u.x*u.x + u.y*u.y + u.z*u.z + u.w*u.w
            + v.x*v.x + v.y*v.y + v.z*v.z + v.w*v.w;
    #pragma unroll
    for (int o = 16; o; o >>= 1) {
        s += __shfl_xor_sync(0xffffffffu, s, o);
        q += __shfl_xor_sync(0xffffffffu, q, o);
    }
    float mean = s * (1.0f / 256.0f);
    float var  = q * (1.0f / 256.0f) - mean * mean;
    float rstd = rsqrtf(var + 1e-5f);

    const float4* gp = (const float4*)gg;
    const float4* bp = (const float4*)bb;
    float4 gu = gp[lane * 2], gv = gp[lane * 2 + 1];
    float4 bu = bp[lane * 2], bv = bp[lane * 2 + 1];

    float4 ou, ov;
    ou.x = (u.x - mean) * rstd * gu.x + bu.x;
    ou.y = (u.y - mean) * rstd * gu.y + bu.y;
    ou.z = (u.z - mean) * rstd * gu.z + bu.z;
    ou.w = (u.w - mean) * rstd * gu.w + bu.w;
    ov.x = (v.x - mean) * rstd * gv.x + bv.x;
    ov.y = (v.y - mean) * rstd * gv.y + bv.y;
    ov.z = (v.z - mean) * rstd * gv.z + bv.z;
    ov.w = (v.w - mean) * rstd * gv.w + bv.w;

    float4* op = (float4*)(g_xn + (size_t)warp * DIMC);
    op[lane * 2]     = ou;
    op[lane * 2 + 1] = ov;
}

// ---------------------------------------------------------------------------
// Tensor-core GEMM (tf32): C[m,n] = sum_k A[m,k] * W[n,k]  (+epilogue)
// Block tile 128x128x32, 8 warps (4 M x 2 N), warp tile 32x64,
// mma.m16n8k8: 2 M-tiles x 8 N-tiles per warp.
// ---------------------------------------------------------------------------
#define EPI_SCALE   0   // C = (acc + bias) * scale
#define EPI_BIAS    1   // C = acc + bias
#define EPI_GELU    2   // C = gelu_exact(acc + bias)
#define EPI_SCATTER 3   // C[map(m)] = acc + bias + R[map(m)]
#define EPI_RESID   4   // C = acc + bias + R[m]

template<int EPI>
__global__ __launch_bounds__(256) void gemm_tc(
    int a_id, const float* __restrict__ W, const float* __restrict__ bias,
    int r_id, const float* __restrict__ r_ext,
    int c_id, float* __restrict__ c_ext,
    int N, int K, float scale)
{
    const float* A = buf(a_id);
    float* C = (c_id >= 0) ? buf(c_id) : c_ext;
    const float* R = nullptr;
    if (EPI == EPI_SCATTER || EPI == EPI_RESID)
        R = (r_id >= 0) ? buf(r_id) : r_ext;

    __shared__ uint32_t As[128][36];   // [m][k], pad 36 -> conflict-free frags
    __shared__ uint32_t Bs[128][36];   // [n][k]

    int tid  = threadIdx.x;
    int lane = tid & 31;
    int wid  = tid >> 5;
    int wm   = wid & 3;      // warp M position (rows wm*32 .. +31)
    int wn   = wid >> 2;     // warp N position (cols wn*64 .. +63)
    int m0 = blockIdx.y * 128, n0 = blockIdx.x * 128;

    // global-load mapping: thread covers rows (lr, lr+64), 2 x float4 per row
    int lr  = tid >> 2;          // 0..63
    int lc4 = (tid & 3) * 4;     // float col 0,4,8,12 (second half +16)

    float acc[2][8][4];
    #pragma unroll
    for (int a = 0; a < 2; a++)
        #pragma unroll
        for (int b = 0; b < 8; b++)
            #pragma unroll
            for (int c = 0; c < 4; c++) acc[a][b][c] = 0.0f;

    for (int kt = 0; kt < K; kt += 32) {
        const float* Ap = A + (size_t)(m0 + lr) * K + kt;
        const float* Wp = W + (size_t)(n0 + lr) * K + kt;
        float4 a0 = *(const float4*)(Ap + lc4);
        float4 a1 = *(const float4*)(Ap + lc4 + 16);
        float4 a2 = *(const float4*)(Ap + (size_t)64 * K + lc4);
        float4 a3 = *(const float4*)(Ap + (size_t)64 * K + lc4 + 16);
        float4 w0 = *(const float4*)(Wp + lc4);
        float4 w1 = *(const float4*)(Wp + lc4 + 16);
        float4 w2 = *(const float4*)(Wp + (size_t)64 * K + lc4);
        float4 w3 = *(const float4*)(Wp + (size_t)64 * K + lc4 + 16);

        __syncthreads();
        *(uint4*)&As[lr][lc4]           = make_uint4(f2tf(a0.x), f2tf(a0.y), f2tf(a0.z), f2tf(a0.w));
        *(uint4*)&As[lr][lc4 + 16]      = make_uint4(f2tf(a1.x), f2tf(a1.y), f2tf(a1.z), f2tf(a1.w));
        *(uint4*)&As[lr + 64][lc4]      = make_uint4(f2tf(a2.x), f2tf(a2.y), f2tf(a2.z), f2tf(a2.w));
        *(uint4*)&As[lr + 64][lc4 + 16] = make_uint4(f2tf(a3.x), f2tf(a3.y), f2tf(a3.z), f2tf(a3.w));
        *(uint4*)&Bs[lr][lc4]           = make_uint4(f2tf(w0.x), f2tf(w0.y), f2tf(w0.z), f2tf(w0.w));
        *(uint4*)&Bs[lr][lc4 + 16]      = make_uint4(f2tf(w1.x), f2tf(w1.y), f2tf(w1.z), f2tf(w1.w));
        *(uint4*)&Bs[lr + 64][lc4]      = make_uint4(f2tf(w2.x), f2tf(w2.y), f2tf(w2.z), f2tf(w2.w));
        *(uint4*)&Bs[lr + 64][lc4 + 16] = make_uint4(f2tf(w3.x), f2tf(w3.y), f2tf(w3.z), f2tf(w3.w));
        __syncthreads();

        #pragma unroll
        for (int ks = 0; ks < 4; ks++) {
            int k0 = ks * 8;
            uint32_t afr[2][4];
            #pragma unroll
            for (int mt = 0; mt < 2; mt++) {
                int rb = wm * 32 + mt * 16 + (lane >> 2);
                int kk = k0 + (lane & 3);
                afr[mt][0] = As[rb][kk];
                afr[mt][1] = As[rb + 8][kk];
                afr[mt][2] = As[rb][kk + 4];
                afr[mt][3] = As[rb + 8][kk + 4];
            }
            #pragma unroll
            for (int nt = 0; nt < 8; nt++) {
                int cb = wn * 64 + nt * 8 + (lane >> 2);
                int kk = k0 + (lane & 3);
                uint32_t b0 = Bs[cb][kk];
                uint32_t b1 = Bs[cb][kk + 4];
                mma_tf32(acc[0][nt], afr[0], b0, b1);
                mma_tf32(acc[1][nt], afr[1], b0, b1);
            }
        }
    }

    // epilogue: c0,c1 -> (row, col), (row, col+1); c2,c3 -> row+8
    #pragma unroll
    for (int mt = 0; mt < 2; mt++) {
        #pragma unroll
        for (int half = 0; half < 2; half++) {
            int row = m0 + wm * 32 + mt * 16 + (lane >> 2) + half * 8;
            size_t crow;
            if (EPI == EPI_SCATTER) crow = (size_t)win_to_flat(row) * N;
            else                    crow = (size_t)row * N;
            #pragma unroll
            for (int nt = 0; nt < 8; nt++) {
                int col = n0 + wn * 64 + nt * 8 + (lane & 3) * 2;
                float v0 = acc[mt][nt][half * 2 + 0] + bias[col];
                float v1 = acc[mt][nt][half * 2 + 1] + bias[col + 1];
                if (EPI == EPI_SCALE) { v0 *= scale; v1 *= scale; }
                if (EPI == EPI_GELU) {
                    v0 = 0.5f * v0 * (1.0f + erff(v0 * 0.70710678118654752f));
                    v1 = 0.5f * v1 * (1.0f + erff(v1 * 0.70710678118654752f));
                }
                if (EPI == EPI_SCATTER || EPI == EPI_RESID) {
                    float2 rr = *(const float2*)&R[crow + col];
                    v0 += rr.x; v1 += rr.y;
                }
                *(float2*)&C[crow + col] = make_float2(v0, v1);
            }
        }
    }
}

// ---------------------------------------------------------------------------
// Attention: one block per (head, window). Restructured LDS:
//  - S compute: warp-uniform j (K rows broadcast, float4), per-lane r.
//  - softmax: 4 threads/row + shuffle.
//  - PV: warp-uniform j (V rows broadcast, float4), per-lane r.
// ---------------------------------------------------------------------------
__global__ __launch_bounds__(256) void attn_k(const float* __restrict__ rpb)
{
    __shared__ float Qs[64][33];    // per-lane row access -> odd-ish pad, scalar
    __shared__ float Ks[64][36];    // broadcast float4 access -> 16B-aligned rows
    __shared__ float Vs[64][36];
    __shared__ float S[64][65];
    __shared__ float bias_s[225];
    __shared__ int   lab[64];

    int h = blockIdx.x;    // 0..7
    int w = blockIdx.y;    // 0..1023
    int tid = threadIdx.x;

    // ---- load Q/K/V tiles (coalesced: 4 lanes cover 32 floats of a row) ----
    {
        int t  = tid >> 2;
        int d0 = (tid & 3) << 3;
        const float* qp = g_q + ((size_t)(w * 64 + t) * 256 + h * 32 + d0);
        float4 a = *(const float4*)qp, b = *(const float4*)(qp + 4);
        Qs[t][d0 + 0] = a.x; Qs[t][d0 + 1] = a.y; Qs[t][d0 + 2] = a.z; Qs[t][d0 + 3] = a.w;
        Qs[t][d0 + 4] = b.x; Qs[t][d0 + 5] = b.y; Qs[t][d0 + 6] = b.z; Qs[t][d0 + 7] = b.w;
        const float* kp = g_kv + ((size_t)(w * 64 + t) * 512 + h * 32 + d0);
        float4 ka = *(const float4*)kp, kb = *(const float4*)(kp + 4);
        *(float4*)&Ks[t][d0]     = ka;
        *(float4*)&Ks[t][d0 + 4] = kb;
        const float* vp = kp + 256;
        float4 va = *(const float4*)vp, vb = *(const float4*)(vp + 4);
        *(float4*)&Vs[t][d0]     = va;
        *(float4*)&Vs[t][d0 + 4] = vb;
    }
    if (tid < 225) bias_s[tid] = rpb[tid * 8 + h];
    if (tid < 64) {
        int wi = w & 63, wr = wi >> 3, wc = wi & 7;
        int rr = tid >> 3, cc = tid & 7;
        int lh = (wr < 7) ? 0 : ((rr < 4) ? 1 : 2);
        int lw = (wc < 7) ? 0 : ((cc < 4) ? 1 : 2);
        lab[tid] = lh * 3 + lw;
    }
    __syncthreads();

    // ---- S = Q K^T + bias + mask.  lane -> row r, warp-uniform col group ----
    {
        int r  = tid & 63;       // 32 distinct rows per warp
        int jg = tid >> 6;       // warp-uniform: cols jg*16 .. +15
        float qreg[32];
        #pragma unroll
        for (int k = 0; k < 32; k++) qreg[k] = Qs[r][k];   // banks (r+k)%32: CF
        int lr_ = lab[r];
        int ri = r >> 3, ci = r & 7;

        #pragma unroll
        for (int jj = 0; jj < 16; jj++) {
            int j = jg * 16 + jj;                 // same for all lanes: broadcast
            float s = 0.0f;
            #pragma unroll
            for (int k4 = 0; k4 < 8; k4++) {
                float4 kv = *(const float4*)&Ks[j][k4 * 4];
                s = fmaf(qreg[k4*4+0], kv.x, s);
                s = fmaf(qreg[k4*4+1], kv.y, s);
                s = fmaf(qreg[k4*4+2], kv.z, s);
                s = fmaf(qreg[k4*4+3], kv.w, s);
            }
            int rj = j >> 3, cj = j & 7;
            s += bias_s[(ri - rj + 7) * 15 + (ci - cj + 7)];
            if (lr_ != lab[j]) s -= 100.0f;
            S[r][j] = s;                          // banks (r+j)%32: CF
        }
    }
    __syncthreads();

    // ---- softmax: 4 threads per row, shuffle-combined ----
    {
        int r = tid >> 2;
        int q = tid & 3;
        float m = -1e30f;
        #pragma unroll
        for (int jj = 0; jj < 16; jj++) m = fmaxf(m, S[r][q * 16 + jj]);
        m = fmaxf(m, __shfl_xor_sync(0xffffffffu, m, 1));
        m = fmaxf(m, __shfl_xor_sync(0xffffffffu, m, 2));
        float sum = 0.0f;
        float e[16];
        #pragma unroll
        for (int jj = 0; jj < 16; jj++) {
            e[jj] = expf(S[r][q * 16 + jj] - m);
            sum += e[jj];
        }
        sum += __shfl_xor_sync(0xffffffffu, sum, 1);
        sum += __shfl_xor_sync(0xffffffffu, sum, 2);
        float inv = 1.0f / sum;
        #pragma unroll
        for (int jj = 0; jj < 16; jj++) S[r][q * 16 + jj] = e[jj] * inv;
    }
    __syncthreads();

    // ---- O = P V.  lane -> row r, warp-uniform d-group ----
    {
        int r  = tid & 63;
        int dg = tid >> 6;
        int d0 = dg * 8;
        float o8[8] = {0, 0, 0, 0, 0, 0, 0, 0};
        #pragma unroll
        for (int j = 0; j < 64; j++) {
            float p = S[r][j];                    // banks (r+j)%32: CF
            float4 v0 = *(const float4*)&Vs[j][d0];       // broadcast
            float4 v1 = *(const float4*)&Vs[j][d0 + 4];
            o8[0] = fmaf(p, v0.x, o8[0]); o8[1] = fmaf(p, v0.y, o8[1]);
            o8[2] = fmaf(p, v0.z, o8[2]); o8[3] = fmaf(p, v0.w, o8[3]);
            o8[4] = fmaf(p, v1.x, o8[4]); o8[5] = fmaf(p, v1.y, o8[5]);
            o8[6] = fmaf(p, v1.z, o8[6]); o8[7] = fmaf(p, v1.w, o8[7]);
        }
        float* op = g_o + ((size_t)(w * 64 + r) * 256 + h * 32 + d0);
        *(float4*)op       = make_float4(o8[0], o8[1], o8[2], o8[3]);
        *(float4*)(op + 4) = make_float4(o8[4], o8[5], o8[6], o8[7]);
    }
}

// ---------------------------------------------------------------------------
// launch
// ---------------------------------------------------------------------------
extern "C" void kernel_launch(void* const* d_in, const int* in_sizes, int n_in,
                              void* d_out, int out_size)
{
    const float* x0   = (const float*)d_in[0];
    const float* x1   = (const float*)d_in[1];
    const float* g1_0 = (const float*)d_in[2];
    const float* b1_0 = (const float*)d_in[3];
    const float* g1_1 = (const float*)d_in[4];
    const float* b1_1 = (const float*)d_in[5];
    const float* Wq   = (const float*)d_in[6];
    const float* bq   = (const float*)d_in[7];
    const float* Wkv  = (const float*)d_in[8];
    const float* bkv  = (const float*)d_in[9];
    const float* rpb  = (const float*)d_in[10];
    const float* Wp   = (const float*)d_in[11];
    const float* bp   = (const float*)d_in[12];
    const float* g2   = (const float*)d_in[13];
    const float* b2   = (const float*)d_in[14];
    const float* Wfc1 = (const float*)d_in[15];
    const float* bfc1 = (const float*)d_in[16];
    const float* Wfc2 = (const float*)d_in[17];
    const float* bfc2 = (const float*)d_in[18];
    float* out = (float*)d_out;

    // 1) LN(x0), LN(x1) + shift + window partition -> g_x0w (0), g_x1w (1)
    ln_win_k<<<16384, 256>>>(x0, x1, g1_0, b1_0, g1_1, b1_1);

    // 2) Q = (x1w @ Wq^T + bq) * scale -> g_q (2)
    gemm_tc<EPI_SCALE><<<dim3(2, 512), 256>>>(1, Wq, bq, -1, nullptr, 2, nullptr,
                                              256, 256, SCALE_Q);
    // 3) KV = x0w @ Wkv^T + bkv -> g_kv (3)
    gemm_tc<EPI_BIAS><<<dim3(4, 512), 256>>>(0, Wkv, bkv, -1, nullptr, 3, nullptr,
                                             512, 256, 1.0f);
    // 4) attention -> g_o (4)
    attn_k<<<dim3(8, 1024), 256>>>(rpb);

    // 5) x = x1 + scatter(attn_out @ Wp^T + bp) -> g_x (5)
    gemm_tc<EPI_SCATTER><<<dim3(2, 512), 256>>>(4, Wp, bp, -1, x1, 5, nullptr,
                                                256, 256, 1.0f);
    // 6) xn = LN2(x) -> g_xn (6)
    ln2_k<<<8192, 256>>>(g2, b2);

    // 7) h = gelu(xn @ Wfc1^T + bfc1) -> g_h (7)
    gemm_tc<EPI_GELU><<<dim3(8, 512), 256>>>(6, Wfc1, bfc1, -1, nullptr, 7, nullptr,
                                             1024, 256, 1.0f);
    // 8) out = x + h @ Wfc2^T + bfc2 -> d_out
    gemm_tc<EPI_RESID><<<dim3(2, 512), 256>>>(7, Wfc2, bfc2, 5, nullptr, -1, out,
                                              256, 1024, 1.0f);
}

// round 12
// speedup vs baseline: 2.4634x; 1.0410x over previous
#include <cuda_runtime.h>
#include <math.h>
#include <stdint.h>

// ---------------------------------------------------------------------------
// Problem constants
//   B=16, H=W=64, DIM=256, HEADS=8, DHEAD=32, WS=8, SHIFT=4
//   N=64 tokens/window, NW=64 windows/image, NTOK = 65536 tokens
// ---------------------------------------------------------------------------
#define NTOK 65536
#define DIMC 256
#define SCALE_Q 0.17677669529663687f   // 32^-0.5

// ---------------------------------------------------------------------------
// Scratch (device globals — no allocations allowed)
// ---------------------------------------------------------------------------
__device__ float g_x0w[(size_t)NTOK * DIMC];        // LN(x0) windowed (tf32-rounded)
__device__ float g_x1w[(size_t)NTOK * DIMC];        // LN(x1) windowed (tf32-rounded)
__device__ float g_q  [(size_t)NTOK * DIMC];        // scaled Q (fp32)
__device__ float g_kv [(size_t)NTOK * 2 * DIMC];    // [K|V] (fp32)
__device__ float g_o  [(size_t)NTOK * DIMC];        // attn out (tf32-rounded)
__device__ float g_x  [(size_t)NTOK * DIMC];        // x = shortcut + attn (fp32)
__device__ float g_xn [(size_t)NTOK * DIMC];        // LN2(x) (tf32-rounded)
__device__ float g_h  [(size_t)NTOK * 1024];        // gelu(fc1) (tf32-rounded)
__device__ float g_wt [786432];                     // tf32-rounded weights

// weight offsets (floats) inside g_wt
#define WOFF_Q   0
#define WOFF_KV  65536
#define WOFF_P   196608
#define WOFF_FC1 262144
#define WOFF_FC2 524288

__device__ __forceinline__ float* buf(int id) {
    switch (id) {
        case 0: return g_x0w;
        case 1: return g_x1w;
        case 2: return g_q;
        case 3: return g_kv;
        case 4: return g_o;
        case 5: return g_x;
        case 6: return g_xn;
        default: return g_h;
    }
}

// windowed row index (w*64+t) -> flat token index (b*4096 + h*64 + w)
__device__ __forceinline__ int win_to_flat(int m) {
    int w  = m >> 6, t = m & 63;
    int b  = w >> 6, wi = w & 63;
    int hs = ((wi >> 3) << 3) + (t >> 3);
    int ws = ((wi & 7) << 3) + (t & 7);
    int hh = (hs + 4) & 63;
    int ww = (ws + 4) & 63;
    return (b << 12) + (hh << 6) + ww;
}

// fp32 -> tf32 round-to-nearest, result as float bit-pattern
__device__ __forceinline__ uint32_t f2tf(float x) {
    uint32_t r;
    asm("cvt.rna.tf32.f32 %0, %1;" : "=r"(r) : "f"(x));
    return r;
}
__device__ __forceinline__ float rtf(float x) { return __uint_as_float(f2tf(x)); }

__device__ __forceinline__ void mma_tf32(float c[4], const uint32_t a[4],
                                         uint32_t b0, uint32_t b1) {
    asm volatile(
        "mma.sync.aligned.m16n8k8.row.col.f32.tf32.tf32.f32 "
        "{%0,%1,%2,%3}, {%4,%5,%6,%7}, {%8,%9}, {%0,%1,%2,%3};\n"
        : "+f"(c[0]), "+f"(c[1]), "+f"(c[2]), "+f"(c[3])
        : "r"(a[0]), "r"(a[1]), "r"(a[2]), "r"(a[3]), "r"(b0), "r"(b1));
}

#define CP16(dst, src) \
    asm volatile("cp.async.ca.shared.global [%0], [%1], 16;" :: "r"(dst), "l"(src))

// ---------------------------------------------------------------------------
// One-shot: round all 5 weight matrices to tf32 into g_wt.
// 196608 float4 elements. grid 768 x 256.
// ---------------------------------------------------------------------------
__global__ __launch_bounds__(256) void cvt_w_k(
    const float* __restrict__ Wq, const float* __restrict__ Wkv,
    const float* __restrict__ Wp, const float* __restrict__ Wfc1,
    const float* __restrict__ Wfc2)
{
    int i4 = blockIdx.x * 256 + threadIdx.x;
    const float* src; int off4;
    if      (i4 < 16384)  { src = Wq;   off4 = 0; }
    else if (i4 < 49152)  { src = Wkv;  off4 = 16384; }
    else if (i4 < 65536)  { src = Wp;   off4 = 49152; }
    else if (i4 < 131072) { src = Wfc1; off4 = 65536; }
    else                  { src = Wfc2; off4 = 131072; }
    float4 v = ((const float4*)src)[i4 - off4];
    ((uint4*)g_wt)[i4] = make_uint4(f2tf(v.x), f2tf(v.y), f2tf(v.z), f2tf(v.w));
}

// ---------------------------------------------------------------------------
// LN(x0), LN(x1) + roll + window partition.  One warp per token.
// Outputs tf32-rounded (consumed only by the Q/KV GEMMs).
// ---------------------------------------------------------------------------
__global__ __launch_bounds__(256) void ln_win_k(
    const float* __restrict__ x0, const float* __restrict__ x1,
    const float* __restrict__ g0, const float* __restrict__ b0,
    const float* __restrict__ g1, const float* __restrict__ b1)
{
    int warp = blockIdx.x * 8 + (threadIdx.x >> 5);
    int lane = threadIdx.x & 31;
    int which = warp >> 16;
    int tok   = warp & (NTOK - 1);
    int flat  = win_to_flat(tok);

    const float* src = which ? x1 : x0;
    const float* gg  = which ? g1 : g0;
    const float* bb  = which ? b1 : b0;
    float* dst       = which ? g_x1w : g_x0w;

    const float4* p = (const float4*)(src + (size_t)flat * DIMC);
    float4 u = p[lane * 2], v = p[lane * 2 + 1];

    float s = u.x + u.y + u.z + u.w + v.x + v.y + v.z + v.w;
    float q = u.x*u.x + u.y*u.y + u.z*u.z + u.w*u.w
            + v.x*v.x + v.y*v.y + v.z*v.z + v.w*v.w;
    #pragma unroll
    for (int o = 16; o; o >>= 1) {
        s += __shfl_xor_sync(0xffffffffu, s, o);
        q += __shfl_xor_sync(0xffffffffu, q, o);
    }
    float mean = s * (1.0f / 256.0f);
    float var  = q * (1.0f / 256.0f) - mean * mean;
    float rstd = rsqrtf(var + 1e-5f);

    const float4* gp = (const float4*)gg;
    const float4* bp = (const float4*)bb;
    float4 gu = gp[lane * 2], gv = gp[lane * 2 + 1];
    float4 bu = bp[lane * 2], bv = bp[lane * 2 + 1];

    float4 ou, ov;
    ou.x = rtf((u.x - mean) * rstd * gu.x + bu.x);
    ou.y = rtf((u.y - mean) * rstd * gu.y + bu.y);
    ou.z = rtf((u.z - mean) * rstd * gu.z + bu.z);
    ou.w = rtf((u.w - mean) * rstd * gu.w + bu.w);
    ov.x = rtf((v.x - mean) * rstd * gv.x + bv.x);
    ov.y = rtf((v.y - mean) * rstd * gv.y + bv.y);
    ov.z = rtf((v.z - mean) * rstd * gv.z + bv.z);
    ov.w = rtf((v.w - mean) * rstd * gv.w + bv.w);

    float4* op = (float4*)(dst + (size_t)tok * DIMC);
    op[lane * 2]     = ou;
    op[lane * 2 + 1] = ov;
}

// ---------------------------------------------------------------------------
// LN2 of g_x -> g_xn (token order), output tf32-rounded (feeds FC1)
// ---------------------------------------------------------------------------
__global__ __launch_bounds__(256) void ln2_k(
    const float* __restrict__ gg, const float* __restrict__ bb)
{
    int warp = blockIdx.x * 8 + (threadIdx.x >> 5);
    int lane = threadIdx.x & 31;

    const float4* p = (const float4*)(g_x + (size_t)warp * DIMC);
    float4 u = p[lane * 2], v = p[lane * 2 + 1];

    float s = u.x + u.y + u.z + u.w + v.x + v.y + v.z + v.w;
    float q = u.x*u.x + u.y*u.y + u.z*u.z + u.w*u.w
            + v.x*v.x + v.y*v.y + v.z*v.z + v.w*v.w;
    #pragma unroll
    for (int o = 16; o; o >>= 1) {
        s += __shfl_xor_sync(0xffffffffu, s, o);
        q += __shfl_xor_sync(0xffffffffu, q, o);
    }
    float mean = s * (1.0f / 256.0f);
    float var  = q * (1.0f / 256.0f) - mean * mean;
    float rstd = rsqrtf(var + 1e-5f);

    const float4* gp = (const float4*)gg;
    const float4* bp = (const float4*)bb;
    float4 gu = gp[lane * 2], gv = gp[lane * 2 + 1];
    float4 bu = bp[lane * 2], bv = bp[lane * 2 + 1];

    float4 ou, ov;
    ou.x = rtf((u.x - mean) * rstd * gu.x + bu.x);
    ou.y = rtf((u.y - mean) * rstd * gu.y + bu.y);
    ou.z = rtf((u.z - mean) * rstd * gu.z + bu.z);
    ou.w = rtf((u.w - mean) * rstd * gu.w + bu.w);
    ov.x = rtf((v.x - mean) * rstd * gv.x + bv.x);
    ov.y = rtf((v.y - mean) * rstd * gv.y + bv.y);
    ov.z = rtf((v.z - mean) * rstd * gv.z + bv.z);
    ov.w = rtf((v.w - mean) * rstd * gv.w + bv.w);

    float4* op = (float4*)(g_xn + (size_t)warp * DIMC);
    op[lane * 2]     = ou;
    op[lane * 2 + 1] = ov;
}

// ---------------------------------------------------------------------------
// Tensor-core GEMM (tf32, cp.async double-buffered):
//   C[m,n] = sum_k A[m,k] * W[n,k]  (+epilogue)
// Operands are already tf32-rounded in gmem -> raw bits to mma.
// Block 128x128x32, 8 warps (4M x 2N), warp 32x64, mma m16n8k8.
// Dynamic smem: 2 * 2 * 128 * 36 u32 = 72 KiB.
// ---------------------------------------------------------------------------
#define EPI_SCALE   0
#define EPI_BIAS    1
#define EPI_GELU    2   // output tf32-rounded (feeds FC2)
#define EPI_SCATTER 3
#define EPI_RESID   4

#define SM_A(bufi, r, k) dyn[((bufi) * 128 + (r)) * 36 + (k)]
#define SM_B(bufi, r, k) dyn[(9216 + ((bufi) * 128 + (r)) * 36) + (k)]

template<int EPI>
__global__ __launch_bounds__(256) void gemm_tc(
    int a_id, int w_off, const float* __restrict__ bias,
    int r_id, const float* __restrict__ r_ext,
    int c_id, float* __restrict__ c_ext,
    int N, int K, float scale)
{
    extern __shared__ uint32_t dyn[];

    const float* A = buf(a_id);
    const float* Wm = g_wt + w_off;
    float* C = (c_id >= 0) ? buf(c_id) : c_ext;
    const float* R = nullptr;
    if (EPI == EPI_SCATTER || EPI == EPI_RESID)
        R = (r_id >= 0) ? buf(r_id) : r_ext;

    int tid  = threadIdx.x;
    int lane = tid & 31;
    int wid  = tid >> 5;
    int wm   = wid & 3;
    int wn   = wid >> 2;
    int m0 = blockIdx.y * 128, n0 = blockIdx.x * 128;

    int lr  = tid >> 2;          // 0..63
    int lc4 = (tid & 3) * 4;     // 0,4,8,12

    uint32_t sbase = (uint32_t)__cvta_generic_to_shared(dyn);
    // this thread's 8 cp.async destinations, per buffer
    uint32_t dA0[2], dA1[2], dA2[2], dA3[2], dB0[2], dB1[2], dB2[2], dB3[2];
    #pragma unroll
    for (int b = 0; b < 2; b++) {
        dA0[b] = sbase + ((b * 128 + lr) * 36 + lc4) * 4;
        dA1[b] = dA0[b] + 64;                 // +16 floats
        dA2[b] = sbase + ((b * 128 + lr + 64) * 36 + lc4) * 4;
        dA3[b] = dA2[b] + 64;
        dB0[b] = dA0[b] + 36864;              // Bs offset = 9216 u32
        dB1[b] = dB0[b] + 64;
        dB2[b] = dA2[b] + 36864;
        dB3[b] = dB2[b] + 64;
    }
    const float* Ap0 = A  + (size_t)(m0 + lr) * K + lc4;
    const float* Ap1 = Ap0 + (size_t)64 * K;
    const float* Wp0 = Wm + (size_t)(n0 + lr) * K + lc4;
    const float* Wp1 = Wp0 + (size_t)64 * K;

    float acc[2][8][4];
    #pragma unroll
    for (int a = 0; a < 2; a++)
        #pragma unroll
        for (int b = 0; b < 8; b++)
            #pragma unroll
            for (int c = 0; c < 4; c++) acc[a][b][c] = 0.0f;

    int ntile = K >> 5;
    // prologue: tile 0 -> buf 0
    CP16(dA0[0], Ap0);      CP16(dA1[0], Ap0 + 16);
    CP16(dA2[0], Ap1);      CP16(dA3[0], Ap1 + 16);
    CP16(dB0[0], Wp0);      CP16(dB1[0], Wp0 + 16);
    CP16(dB2[0], Wp1);      CP16(dB3[0], Wp1 + 16);
    asm volatile("cp.async.commit_group;");

    for (int t = 0; t < ntile; t++) {
        int cur = t & 1;
        if (t + 1 < ntile) {
            int kt = (t + 1) << 5;
            int nb = cur ^ 1;
            CP16(dA0[nb], Ap0 + kt);      CP16(dA1[nb], Ap0 + kt + 16);
            CP16(dA2[nb], Ap1 + kt);      CP16(dA3[nb], Ap1 + kt + 16);
            CP16(dB0[nb], Wp0 + kt);      CP16(dB1[nb], Wp0 + kt + 16);
            CP16(dB2[nb], Wp1 + kt);      CP16(dB3[nb], Wp1 + kt + 16);
            asm volatile("cp.async.commit_group;");
            asm volatile("cp.async.wait_group 1;");
        } else {
            asm volatile("cp.async.wait_group 0;");
        }
        __syncthreads();

        #pragma unroll
        for (int ks = 0; ks < 4; ks++) {
            int k0 = ks * 8;
            int kk = k0 + (lane & 3);
            uint32_t afr[2][4];
            #pragma unroll
            for (int mt = 0; mt < 2; mt++) {
                int rb = wm * 32 + mt * 16 + (lane >> 2);
                afr[mt][0] = SM_A(cur, rb, kk);
                afr[mt][1] = SM_A(cur, rb + 8, kk);
                afr[mt][2] = SM_A(cur, rb, kk + 4);
                afr[mt][3] = SM_A(cur, rb + 8, kk + 4);
            }
            #pragma unroll
            for (int nt = 0; nt < 8; nt++) {
                int cb = wn * 64 + nt * 8 + (lane >> 2);
                uint32_t b0 = SM_B(cur, cb, kk);
                uint32_t b1 = SM_B(cur, cb, kk + 4);
                mma_tf32(acc[0][nt], afr[0], b0, b1);
                mma_tf32(acc[1][nt], afr[1], b0, b1);
            }
        }
        __syncthreads();
    }

    #pragma unroll
    for (int mt = 0; mt < 2; mt++) {
        #pragma unroll
        for (int half = 0; half < 2; half++) {
            int row = m0 + wm * 32 + mt * 16 + (lane >> 2) + half * 8;
            size_t crow;
            if (EPI == EPI_SCATTER) crow = (size_t)win_to_flat(row) * N;
            else                    crow = (size_t)row * N;
            #pragma unroll
            for (int nt = 0; nt < 8; nt++) {
                int col = n0 + wn * 64 + nt * 8 + (lane & 3) * 2;
                float v0 = acc[mt][nt][half * 2 + 0] + bias[col];
                float v1 = acc[mt][nt][half * 2 + 1] + bias[col + 1];
                if (EPI == EPI_SCALE) { v0 *= scale; v1 *= scale; }
                if (EPI == EPI_GELU) {
                    v0 = rtf(0.5f * v0 * (1.0f + erff(v0 * 0.70710678118654752f)));
                    v1 = rtf(0.5f * v1 * (1.0f + erff(v1 * 0.70710678118654752f)));
                }
                if (EPI == EPI_SCATTER || EPI == EPI_RESID) {
                    float2 rr = *(const float2*)&R[crow + col];
                    v0 += rr.x; v1 += rr.y;
                }
                *(float2*)&C[crow + col] = make_float2(v0, v1);
            }
        }
    }
}

// ---------------------------------------------------------------------------
// Attention: one block per (head, window). Output tf32-rounded (feeds proj).
// ---------------------------------------------------------------------------
__global__ __launch_bounds__(256) void attn_k(const float* __restrict__ rpb)
{
    __shared__ float Qs[64][33];
    __shared__ float Ks[64][36];
    __shared__ float Vs[64][36];
    __shared__ float S[64][65];
    __shared__ float bias_s[225];
    __shared__ int   lab[64];

    int h = blockIdx.x;
    int w = blockIdx.y;
    int tid = threadIdx.x;

    {
        int t  = tid >> 2;
        int d0 = (tid & 3) << 3;
        const float* qp = g_q + ((size_t)(w * 64 + t) * 256 + h * 32 + d0);
        float4 a = *(const float4*)qp, b = *(const float4*)(qp + 4);
        Qs[t][d0 + 0] = a.x; Qs[t][d0 + 1] = a.y; Qs[t][d0 + 2] = a.z; Qs[t][d0 + 3] = a.w;
        Qs[t][d0 + 4] = b.x; Qs[t][d0 + 5] = b.y; Qs[t][d0 + 6] = b.z; Qs[t][d0 + 7] = b.w;
        const float* kp = g_kv + ((size_t)(w * 64 + t) * 512 + h * 32 + d0);
        float4 ka = *(const float4*)kp, kb = *(const float4*)(kp + 4);
        *(float4*)&Ks[t][d0]     = ka;
        *(float4*)&Ks[t][d0 + 4] = kb;
        const float* vp = kp + 256;
        float4 va = *(const float4*)vp, vb = *(const float4*)(vp + 4);
        *(float4*)&Vs[t][d0]     = va;
        *(float4*)&Vs[t][d0 + 4] = vb;
    }
    if (tid < 225) bias_s[tid] = rpb[tid * 8 + h];
    if (tid < 64) {
        int wi = w & 63, wr = wi >> 3, wc = wi & 7;
        int rr = tid >> 3, cc = tid & 7;
        int lh = (wr < 7) ? 0 : ((rr < 4) ? 1 : 2);
        int lw = (wc < 7) ? 0 : ((cc < 4) ? 1 : 2);
        lab[tid] = lh * 3 + lw;
    }
    __syncthreads();

    {
        int r  = tid & 63;
        int jg = tid >> 6;
        float qreg[32];
        #pragma unroll
        for (int k = 0; k < 32; k++) qreg[k] = Qs[r][k];
        int lr_ = lab[r];
        int ri = r >> 3, ci = r & 7;

        #pragma unroll
        for (int jj = 0; jj < 16; jj++) {
            int j = jg * 16 + jj;
            float s = 0.0f;
            #pragma unroll
            for (int k4 = 0; k4 < 8; k4++) {
                float4 kv = *(const float4*)&Ks[j][k4 * 4];
                s = fmaf(qreg[k4*4+0], kv.x, s);
                s = fmaf(qreg[k4*4+1], kv.y, s);
                s = fmaf(qreg[k4*4+2], kv.z, s);
                s = fmaf(qreg[k4*4+3], kv.w, s);
            }
            int rj = j >> 3, cj = j & 7;
            s += bias_s[(ri - rj + 7) * 15 + (ci - cj + 7)];
            if (lr_ != lab[j]) s -= 100.0f;
            S[r][j] = s;
        }
    }
    __syncthreads();

    {
        int r = tid >> 2;
        int q = tid & 3;
        float m = -1e30f;
        #pragma unroll
        for (int jj = 0; jj < 16; jj++) m = fmaxf(m, S[r][q * 16 + jj]);
        m = fmaxf(m, __shfl_xor_sync(0xffffffffu, m, 1));
        m = fmaxf(m, __shfl_xor_sync(0xffffffffu, m, 2));
        float sum = 0.0f;
        float e[16];
        #pragma unroll
        for (int jj = 0; jj < 16; jj++) {
            e[jj] = expf(S[r][q * 16 + jj] - m);
            sum += e[jj];
        }
        sum += __shfl_xor_sync(0xffffffffu, sum, 1);
        sum += __shfl_xor_sync(0xffffffffu, sum, 2);
        float inv = 1.0f / sum;
        #pragma unroll
        for (int jj = 0; jj < 16; jj++) S[r][q * 16 + jj] = e[jj] * inv;
    }
    __syncthreads();

    {
        int r  = tid & 63;
        int dg = tid >> 6;
        int d0 = dg * 8;
        float o8[8] = {0, 0, 0, 0, 0, 0, 0, 0};
        #pragma unroll
        for (int j = 0; j < 64; j++) {
            float p = S[r][j];
            float4 v0 = *(const float4*)&Vs[j][d0];
            float4 v1 = *(const float4*)&Vs[j][d0 + 4];
            o8[0] = fmaf(p, v0.x, o8[0]); o8[1] = fmaf(p, v0.y, o8[1]);
            o8[2] = fmaf(p, v0.z, o8[2]); o8[3] = fmaf(p, v0.w, o8[3]);
            o8[4] = fmaf(p, v1.x, o8[4]); o8[5] = fmaf(p, v1.y, o8[5]);
            o8[6] = fmaf(p, v1.z, o8[6]); o8[7] = fmaf(p, v1.w, o8[7]);
        }
        float* op = g_o + ((size_t)(w * 64 + r) * 256 + h * 32 + d0);
        *(float4*)op       = make_float4(rtf(o8[0]), rtf(o8[1]), rtf(o8[2]), rtf(o8[3]));
        *(float4*)(op + 4) = make_float4(rtf(o8[4]), rtf(o8[5]), rtf(o8[6]), rtf(o8[7]));
    }
}

// ---------------------------------------------------------------------------
// launch
// ---------------------------------------------------------------------------
#define GEMM_SMEM 73728

extern "C" void kernel_launch(void* const* d_in, const int* in_sizes, int n_in,
                              void* d_out, int out_size)
{
    const float* x0   = (const float*)d_in[0];
    const float* x1   = (const float*)d_in[1];
    const float* g1_0 = (const float*)d_in[2];
    const float* b1_0 = (const float*)d_in[3];
    const float* g1_1 = (const float*)d_in[4];
    const float* b1_1 = (const float*)d_in[5];
    const float* Wq   = (const float*)d_in[6];
    const float* bq   = (const float*)d_in[7];
    const float* Wkv  = (const float*)d_in[8];
    const float* bkv  = (const float*)d_in[9];
    const float* rpb  = (const float*)d_in[10];
    const float* Wp   = (const float*)d_in[11];
    const float* bp   = (const float*)d_in[12];
    const float* g2   = (const float*)d_in[13];
    const float* b2   = (const float*)d_in[14];
    const float* Wfc1 = (const float*)d_in[15];
    const float* bfc1 = (const float*)d_in[16];
    const float* Wfc2 = (const float*)d_in[17];
    const float* bfc2 = (const float*)d_in[18];
    float* out = (float*)d_out;

    static bool attr_done = false;
    if (!attr_done) {
        cudaFuncSetAttribute(gemm_tc<EPI_SCALE>,   cudaFuncAttributeMaxDynamicSharedMemorySize, GEMM_SMEM);
        cudaFuncSetAttribute(gemm_tc<EPI_BIAS>,    cudaFuncAttributeMaxDynamicSharedMemorySize, GEMM_SMEM);
        cudaFuncSetAttribute(gemm_tc<EPI_GELU>,    cudaFuncAttributeMaxDynamicSharedMemorySize, GEMM_SMEM);
        cudaFuncSetAttribute(gemm_tc<EPI_SCATTER>, cudaFuncAttributeMaxDynamicSharedMemorySize, GEMM_SMEM);
        cudaFuncSetAttribute(gemm_tc<EPI_RESID>,   cudaFuncAttributeMaxDynamicSharedMemorySize, GEMM_SMEM);
        attr_done = true;
    }

    // 0) weights -> tf32 scratch
    cvt_w_k<<<768, 256>>>(Wq, Wkv, Wp, Wfc1, Wfc2);

    // 1) LN(x0), LN(x1) + shift + window partition -> g_x0w (0), g_x1w (1)
    ln_win_k<<<16384, 256>>>(x0, x1, g1_0, b1_0, g1_1, b1_1);

    // 2) Q = (x1w @ Wq^T + bq) * scale -> g_q (2)
    gemm_tc<EPI_SCALE><<<dim3(2, 512), 256, GEMM_SMEM>>>(1, WOFF_Q, bq, -1, nullptr,
                                                         2, nullptr, 256, 256, SCALE_Q);
    // 3) KV = x0w @ Wkv^T + bkv -> g_kv (3)
    gemm_tc<EPI_BIAS><<<dim3(4, 512), 256, GEMM_SMEM>>>(0, WOFF_KV, bkv, -1, nullptr,
                                                        3, nullptr, 512, 256, 1.0f);
    // 4) attention -> g_o (4)
    attn_k<<<dim3(8, 1024), 256>>>(rpb);

    // 5) x = x1 + scatter(attn_out @ Wp^T + bp) -> g_x (5)
    gemm_tc<EPI_SCATTER><<<dim3(2, 512), 256, GEMM_SMEM>>>(4, WOFF_P, bp, -1, x1,
                                                           5, nullptr, 256, 256, 1.0f);
    // 6) xn = LN2(x) -> g_xn (6)
    ln2_k<<<8192, 256>>>(g2, b2);

    // 7) h = gelu(xn @ Wfc1^T + bfc1) -> g_h (7)
    gemm_tc<EPI_GELU><<<dim3(8, 512), 256, GEMM_SMEM>>>(6, WOFF_FC1, bfc1, -1, nullptr,
                                                        7, nullptr, 1024, 256, 1.0f);
    // 8) out = x + h @ Wfc2^T + bfc2 -> d_out
    gemm_tc<EPI_RESID><<<dim3(2, 512), 256, GEMM_SMEM>>>(7, WOFF_FC2, bfc2, 5, nullptr,
                                                         -1, out, 256, 1024, 1.0f);
}

// round 13
// speedup vs baseline: 3.6170x; 1.4683x over previous
#include <cuda_runtime.h>
#include <cuda_bf16.h>
#include <math.h>
#include <stdint.h>

// ---------------------------------------------------------------------------
// Problem constants
//   B=16, H=W=64, DIM=256, HEADS=8, DHEAD=32, WS=8, SHIFT=4
//   N=64 tokens/window, NW=64 windows/image, NTOK = 65536 tokens
// ---------------------------------------------------------------------------
#define NTOK 65536
#define DIMC 256
#define SCALE_Q 0.17677669529663687f   // 32^-0.5

// ---------------------------------------------------------------------------
// Scratch (device globals — no allocations allowed)
// GEMM A-operands / weights stored bf16; everything else fp32.
// ---------------------------------------------------------------------------
__device__ __nv_bfloat16 g_x0w[(size_t)NTOK * DIMC];   // LN(x0) windowed
__device__ __nv_bfloat16 g_x1w[(size_t)NTOK * DIMC];   // LN(x1) windowed
__device__ float         g_q  [(size_t)NTOK * DIMC];   // scaled Q (fp32, attn)
__device__ float         g_kv [(size_t)NTOK * 2 * DIMC]; // [K|V] (fp32, attn)
__device__ __nv_bfloat16 g_o  [(size_t)NTOK * DIMC];   // attn out (feeds proj)
__device__ float         g_x  [(size_t)NTOK * DIMC];   // x = shortcut + attn
__device__ __nv_bfloat16 g_xn [(size_t)NTOK * DIMC];   // LN2(x) (feeds FC1)
__device__ __nv_bfloat16 g_h  [(size_t)NTOK * 1024];   // gelu(fc1) (feeds FC2)
__device__ __nv_bfloat16 g_wb [786432];                // bf16 weights

// weight offsets (elements) inside g_wb
#define WOFF_Q   0
#define WOFF_KV  65536
#define WOFF_P   196608
#define WOFF_FC1 262144
#define WOFF_FC2 524288

__device__ __forceinline__ const __nv_bfloat16* abuf(int id) {
    switch (id) {
        case 0: return g_x0w;
        case 1: return g_x1w;
        case 4: return g_o;
        case 6: return g_xn;
        default: return g_h;
    }
}
__device__ __forceinline__ float* cbuf(int id) {
    switch (id) {
        case 2: return g_q;
        case 3: return g_kv;
        default: return g_x;
    }
}

// windowed row index (w*64+t) -> flat token index (b*4096 + h*64 + w)
__device__ __forceinline__ int win_to_flat(int m) {
    int w  = m >> 6, t = m & 63;
    int b  = w >> 6, wi = w & 63;
    int hs = ((wi >> 3) << 3) + (t >> 3);
    int ws = ((wi & 7) << 3) + (t & 7);
    int hh = (hs + 4) & 63;
    int ww = (ws + 4) & 63;
    return (b << 12) + (hh << 6) + ww;
}

__device__ __forceinline__ uint32_t bf2(float lo, float hi) {
    __nv_bfloat162 h = __floats2bfloat162_rn(lo, hi);
    return *(uint32_t*)&h;
}

__device__ __forceinline__ void mma_bf16(float c[4], const uint32_t a[4],
                                         uint32_t b0, uint32_t b1) {
    asm volatile(
        "mma.sync.aligned.m16n8k16.row.col.f32.bf16.bf16.f32 "
        "{%0,%1,%2,%3}, {%4,%5,%6,%7}, {%8,%9}, {%0,%1,%2,%3};\n"
        : "+f"(c[0]), "+f"(c[1]), "+f"(c[2]), "+f"(c[3])
        : "r"(a[0]), "r"(a[1]), "r"(a[2]), "r"(a[3]), "r"(b0), "r"(b1));
}

#define CP16(dst, src) \
    asm volatile("cp.async.ca.shared.global [%0], [%1], 16;" :: "r"(dst), "l"(src))

// ---------------------------------------------------------------------------
// One-shot: weights fp32 -> bf16 into g_wb.  196608 float4 -> uint2.
// ---------------------------------------------------------------------------
__global__ __launch_bounds__(256) void cvt_w_k(
    const float* __restrict__ Wq, const float* __restrict__ Wkv,
    const float* __restrict__ Wp, const float* __restrict__ Wfc1,
    const float* __restrict__ Wfc2)
{
    int i4 = blockIdx.x * 256 + threadIdx.x;
    const float* src; int off4;
    if      (i4 < 16384)  { src = Wq;   off4 = 0; }
    else if (i4 < 49152)  { src = Wkv;  off4 = 16384; }
    else if (i4 < 65536)  { src = Wp;   off4 = 49152; }
    else if (i4 < 131072) { src = Wfc1; off4 = 65536; }
    else                  { src = Wfc2; off4 = 131072; }
    float4 v = ((const float4*)src)[i4 - off4];
    ((uint2*)g_wb)[i4] = make_uint2(bf2(v.x, v.y), bf2(v.z, v.w));
}

// ---------------------------------------------------------------------------
// LN(x0), LN(x1) + roll + window partition.  One warp per token. bf16 out.
// ---------------------------------------------------------------------------
__global__ __launch_bounds__(256) void ln_win_k(
    const float* __restrict__ x0, const float* __restrict__ x1,
    const float* __restrict__ g0, const float* __restrict__ b0,
    const float* __restrict__ g1, const float* __restrict__ b1)
{
    int warp = blockIdx.x * 8 + (threadIdx.x >> 5);
    int lane = threadIdx.x & 31;
    int which = warp >> 16;
    int tok   = warp & (NTOK - 1);
    int flat  = win_to_flat(tok);

    const float* src = which ? x1 : x0;
    const float* gg  = which ? g1 : g0;
    const float* bb  = which ? b1 : b0;
    __nv_bfloat16* dst = which ? g_x1w : g_x0w;

    const float4* p = (const float4*)(src + (size_t)flat * DIMC);
    float4 u = p[lane * 2], v = p[lane * 2 + 1];

    float s = u.x + u.y + u.z + u.w + v.x + v.y + v.z + v.w;
    float q = u.x*u.x + u.y*u.y + u.z*u.z + u.w*u.w
            + v.x*v.x + v.y*v.y + v.z*v.z + v.w*v.w;
    #pragma unroll
    for (int o = 16; o; o >>= 1) {
        s += __shfl_xor_sync(0xffffffffu, s, o);
        q += __shfl_xor_sync(0xffffffffu, q, o);
    }
    float mean = s * (1.0f / 256.0f);
    float var  = q * (1.0f / 256.0f) - mean * mean;
    float rstd = rsqrtf(var + 1e-5f);

    const float4* gp = (const float4*)gg;
    const float4* bp = (const float4*)bb;
    float4 gu = gp[lane * 2], gv = gp[lane * 2 + 1];
    float4 bu = bp[lane * 2], bv = bp[lane * 2 + 1];

    uint4 o4;
    o4.x = bf2((u.x - mean) * rstd * gu.x + bu.x, (u.y - mean) * rstd * gu.y + bu.y);
    o4.y = bf2((u.z - mean) * rstd * gu.z + bu.z, (u.w - mean) * rstd * gu.w + bu.w);
    o4.z = bf2((v.x - mean) * rstd * gv.x + bv.x, (v.y - mean) * rstd * gv.y + bv.y);
    o4.w = bf2((v.z - mean) * rstd * gv.z + bv.z, (v.w - mean) * rstd * gv.w + bv.w);
    ((uint4*)(dst + (size_t)tok * DIMC))[lane] = o4;
}

// ---------------------------------------------------------------------------
// LN2 of g_x -> g_xn (token order), bf16 out
// ---------------------------------------------------------------------------
__global__ __launch_bounds__(256) void ln2_k(
    const float* __restrict__ gg, const float* __restrict__ bb)
{
    int warp = blockIdx.x * 8 + (threadIdx.x >> 5);
    int lane = threadIdx.x & 31;

    const float4* p = (const float4*)(g_x + (size_t)warp * DIMC);
    float4 u = p[lane * 2], v = p[lane * 2 + 1];

    float s = u.x + u.y + u.z + u.w + v.x + v.y + v.z + v.w;
    float q = u.x*u.x + u.y*u.y + u.z*u.z + u.w*u.w
            + v.x*v.x + v.y*v.y + v.z*v.z + v.w*v.w;
    #pragma unroll
    for (int o = 16; o; o >>= 1) {
        s += __shfl_xor_sync(0xffffffffu, s, o);
        q += __shfl_xor_sync(0xffffffffu, q, o);
    }
    float mean = s * (1.0f / 256.0f);
    float var  = q * (1.0f / 256.0f) - mean * mean;
    float rstd = rsqrtf(var + 1e-5f);

    const float4* gp = (const float4*)gg;
    const float4* bp = (const float4*)bb;
    float4 gu = gp[lane * 2], gv = gp[lane * 2 + 1];
    float4 bu = bp[lane * 2], bv = bp[lane * 2 + 1];

    uint4 o4;
    o4.x = bf2((u.x - mean) * rstd * gu.x + bu.x, (u.y - mean) * rstd * gu.y + bu.y);
    o4.y = bf2((u.z - mean) * rstd * gu.z + bu.z, (u.w - mean) * rstd * gu.w + bu.w);
    o4.z = bf2((v.x - mean) * rstd * gv.x + bv.x, (v.y - mean) * rstd * gv.y + bv.y);
    o4.w = bf2((v.z - mean) * rstd * gv.z + bv.z, (v.w - mean) * rstd * gv.w + bv.w);
    ((uint4*)(g_xn + (size_t)warp * DIMC))[lane] = o4;
}

// ---------------------------------------------------------------------------
// bf16 tensor-core GEMM (cp.async double-buffered):
//   C[m,n] = sum_k A[m,k] * W[n,k]  (+epilogue)
// A, W bf16 row-major; C fp32 (or bf16 for OUTBF).
// Block 128x128x32, 8 warps (4M x 2N), warp 32x64, mma m16n8k16 (2 k-steps).
// Smem: u32 bf16x2 rows, pitch 20 u32 (conflict-free 8x4 frag pattern). 40 KiB.
// ---------------------------------------------------------------------------
#define EPI_SCALE   0
#define EPI_BIAS    1
#define EPI_GELU    2
#define EPI_SCATTER 3
#define EPI_RESID   4

template<int EPI, bool OUTBF>
__global__ __launch_bounds__(256) void gemm_tc(
    int a_id, int w_off, const float* __restrict__ bias,
    int r_id, const float* __restrict__ r_ext,
    int c_id, float* __restrict__ c_ext,
    int N, int K, float scale)
{
    __shared__ uint32_t As[2][128][20];   // u32 = bf16x2, cols 0..15 used
    __shared__ uint32_t Bs[2][128][20];

    const __nv_bfloat16* A  = abuf(a_id);
    const __nv_bfloat16* Wm = g_wb + w_off;
    float* C = nullptr;
    if (!OUTBF) C = (c_id >= 0) ? cbuf(c_id) : c_ext;
    const float* R = nullptr;
    if (EPI == EPI_SCATTER || EPI == EPI_RESID)
        R = (r_id >= 0) ? cbuf(r_id) : r_ext;

    int tid  = threadIdx.x;
    int lane = tid & 31;
    int wid  = tid >> 5;
    int wm   = wid & 3;
    int wn   = wid >> 2;
    int m0 = blockIdx.y * 128, n0 = blockIdx.x * 128;

    int lr  = tid >> 2;          // 0..63
    int lc  = (tid & 3) * 4;     // u32 col 0,4,8,12 (16B chunk)

    uint32_t ab = (uint32_t)__cvta_generic_to_shared(&As[0][0][0]);
    uint32_t bb_ = (uint32_t)__cvta_generic_to_shared(&Bs[0][0][0]);
    uint32_t dA0[2], dA1[2], dB0[2], dB1[2];
    #pragma unroll
    for (int b = 0; b < 2; b++) {
        dA0[b] = ab + ((b * 128 + lr) * 20 + lc) * 4;
        dA1[b] = ab + ((b * 128 + lr + 64) * 20 + lc) * 4;
        dB0[b] = bb_ + ((b * 128 + lr) * 20 + lc) * 4;
        dB1[b] = bb_ + ((b * 128 + lr + 64) * 20 + lc) * 4;
    }
    const __nv_bfloat16* Ap0 = A  + (size_t)(m0 + lr) * K + lc * 2;
    const __nv_bfloat16* Ap1 = Ap0 + (size_t)64 * K;
    const __nv_bfloat16* Wp0 = Wm + (size_t)(n0 + lr) * K + lc * 2;
    const __nv_bfloat16* Wp1 = Wp0 + (size_t)64 * K;

    float acc[2][8][4];
    #pragma unroll
    for (int a = 0; a < 2; a++)
        #pragma unroll
        for (int b = 0; b < 8; b++)
            #pragma unroll
            for (int c = 0; c < 4; c++) acc[a][b][c] = 0.0f;

    int ntile = K >> 5;
    CP16(dA0[0], Ap0);  CP16(dA1[0], Ap1);
    CP16(dB0[0], Wp0);  CP16(dB1[0], Wp1);
    asm volatile("cp.async.commit_group;");

    for (int t = 0; t < ntile; t++) {
        int cur = t & 1;
        if (t + 1 < ntile) {
            int kt = (t + 1) << 5;      // bf16 elements
            int nb = cur ^ 1;
            CP16(dA0[nb], Ap0 + kt);  CP16(dA1[nb], Ap1 + kt);
            CP16(dB0[nb], Wp0 + kt);  CP16(dB1[nb], Wp1 + kt);
            asm volatile("cp.async.commit_group;");
            asm volatile("cp.async.wait_group 1;");
        } else {
            asm volatile("cp.async.wait_group 0;");
        }
        __syncthreads();

        #pragma unroll
        for (int ks = 0; ks < 2; ks++) {          // k-step of 16 = 8 u32
            int kk = ks * 8 + (lane & 3);
            uint32_t afr[2][4];
            #pragma unroll
            for (int mt = 0; mt < 2; mt++) {
                int rb = wm * 32 + mt * 16 + (lane >> 2);
                afr[mt][0] = As[cur][rb][kk];
                afr[mt][1] = As[cur][rb + 8][kk];
                afr[mt][2] = As[cur][rb][kk + 4];
                afr[mt][3] = As[cur][rb + 8][kk + 4];
            }
            #pragma unroll
            for (int nt = 0; nt < 8; nt++) {
                int cb = wn * 64 + nt * 8 + (lane >> 2);
                uint32_t b0 = Bs[cur][cb][kk];
                uint32_t b1 = Bs[cur][cb][kk + 4];
                mma_bf16(acc[0][nt], afr[0], b0, b1);
                mma_bf16(acc[1][nt], afr[1], b0, b1);
            }
        }
        __syncthreads();
    }

    #pragma unroll
    for (int mt = 0; mt < 2; mt++) {
        #pragma unroll
        for (int half = 0; half < 2; half++) {
            int row = m0 + wm * 32 + mt * 16 + (lane >> 2) + half * 8;
            size_t crow;
            if (EPI == EPI_SCATTER) crow = (size_t)win_to_flat(row) * N;
            else                    crow = (size_t)row * N;
            #pragma unroll
            for (int nt = 0; nt < 8; nt++) {
                int col = n0 + wn * 64 + nt * 8 + (lane & 3) * 2;
                float v0 = acc[mt][nt][half * 2 + 0] + bias[col];
                float v1 = acc[mt][nt][half * 2 + 1] + bias[col + 1];
                if (EPI == EPI_SCALE) { v0 *= scale; v1 *= scale; }
                if (EPI == EPI_GELU) {
                    v0 = 0.5f * v0 * (1.0f + erff(v0 * 0.70710678118654752f));
                    v1 = 0.5f * v1 * (1.0f + erff(v1 * 0.70710678118654752f));
                }
                if (EPI == EPI_SCATTER || EPI == EPI_RESID) {
                    float2 rr = *(const float2*)&R[crow + col];
                    v0 += rr.x; v1 += rr.y;
                }
                if (OUTBF) {
                    *(uint32_t*)&g_h[crow + col] = bf2(v0, v1);
                } else {
                    *(float2*)&C[crow + col] = make_float2(v0, v1);
                }
            }
        }
    }
}

// ---------------------------------------------------------------------------
// Attention: one block per (head, window). bf16 output (feeds proj GEMM).
// ---------------------------------------------------------------------------
__global__ __launch_bounds__(256) void attn_k(const float* __restrict__ rpb)
{
    __shared__ float Qs[64][33];
    __shared__ float Ks[64][36];
    __shared__ float Vs[64][36];
    __shared__ float S[64][65];
    __shared__ float bias_s[225];
    __shared__ int   lab[64];

    int h = blockIdx.x;
    int w = blockIdx.y;
    int tid = threadIdx.x;

    {
        int t  = tid >> 2;
        int d0 = (tid & 3) << 3;
        const float* qp = g_q + ((size_t)(w * 64 + t) * 256 + h * 32 + d0);
        float4 a = *(const float4*)qp, b = *(const float4*)(qp + 4);
        Qs[t][d0 + 0] = a.x; Qs[t][d0 + 1] = a.y; Qs[t][d0 + 2] = a.z; Qs[t][d0 + 3] = a.w;
        Qs[t][d0 + 4] = b.x; Qs[t][d0 + 5] = b.y; Qs[t][d0 + 6] = b.z; Qs[t][d0 + 7] = b.w;
        const float* kp = g_kv + ((size_t)(w * 64 + t) * 512 + h * 32 + d0);
        float4 ka = *(const float4*)kp, kb = *(const float4*)(kp + 4);
        *(float4*)&Ks[t][d0]     = ka;
        *(float4*)&Ks[t][d0 + 4] = kb;
        const float* vp = kp + 256;
        float4 va = *(const float4*)vp, vb = *(const float4*)(vp + 4);
        *(float4*)&Vs[t][d0]     = va;
        *(float4*)&Vs[t][d0 + 4] = vb;
    }
    if (tid < 225) bias_s[tid] = rpb[tid * 8 + h];
    if (tid < 64) {
        int wi = w & 63, wr = wi >> 3, wc = wi & 7;
        int rr = tid >> 3, cc = tid & 7;
        int lh = (wr < 7) ? 0 : ((rr < 4) ? 1 : 2);
        int lw = (wc < 7) ? 0 : ((cc < 4) ? 1 : 2);
        lab[tid] = lh * 3 + lw;
    }
    __syncthreads();

    {
        int r  = tid & 63;
        int jg = tid >> 6;
        float qreg[32];
        #pragma unroll
        for (int k = 0; k < 32; k++) qreg[k] = Qs[r][k];
        int lr_ = lab[r];
        int ri = r >> 3, ci = r & 7;

        #pragma unroll
        for (int jj = 0; jj < 16; jj++) {
            int j = jg * 16 + jj;
            float s = 0.0f;
            #pragma unroll
            for (int k4 = 0; k4 < 8; k4++) {
                float4 kv = *(const float4*)&Ks[j][k4 * 4];
                s = fmaf(qreg[k4*4+0], kv.x, s);
                s = fmaf(qreg[k4*4+1], kv.y, s);
                s = fmaf(qreg[k4*4+2], kv.z, s);
                s = fmaf(qreg[k4*4+3], kv.w, s);
            }
            int rj = j >> 3, cj = j & 7;
            s += bias_s[(ri - rj + 7) * 15 + (ci - cj + 7)];
            if (lr_ != lab[j]) s -= 100.0f;
            S[r][j] = s;
        }
    }
    __syncthreads();

    {
        int r = tid >> 2;
        int q = tid & 3;
        float m = -1e30f;
        #pragma unroll
        for (int jj = 0; jj < 16; jj++) m = fmaxf(m, S[r][q * 16 + jj]);
        m = fmaxf(m, __shfl_xor_sync(0xffffffffu, m, 1));
        m = fmaxf(m, __shfl_xor_sync(0xffffffffu, m, 2));
        float sum = 0.0f;
        float e[16];
        #pragma unroll
        for (int jj = 0; jj < 16; jj++) {
            e[jj] = expf(S[r][q * 16 + jj] - m);
            sum += e[jj];
        }
        sum += __shfl_xor_sync(0xffffffffu, sum, 1);
        sum += __shfl_xor_sync(0xffffffffu, sum, 2);
        float inv = 1.0f / sum;
        #pragma unroll
        for (int jj = 0; jj < 16; jj++) S[r][q * 16 + jj] = e[jj] * inv;
    }
    __syncthreads();

    {
        int r  = tid & 63;
        int dg = tid >> 6;
        int d0 = dg * 8;
        float o8[8] = {0, 0, 0, 0, 0, 0, 0, 0};
        #pragma unroll
        for (int j = 0; j < 64; j++) {
            float p = S[r][j];
            float4 v0 = *(const float4*)&Vs[j][d0];
            float4 v1 = *(const float4*)&Vs[j][d0 + 4];
            o8[0] = fmaf(p, v0.x, o8[0]); o8[1] = fmaf(p, v0.y, o8[1]);
            o8[2] = fmaf(p, v0.z, o8[2]); o8[3] = fmaf(p, v0.w, o8[3]);
            o8[4] = fmaf(p, v1.x, o8[4]); o8[5] = fmaf(p, v1.y, o8[5]);
            o8[6] = fmaf(p, v1.z, o8[6]); o8[7] = fmaf(p, v1.w, o8[7]);
        }
        uint4 o4 = make_uint4(bf2(o8[0], o8[1]), bf2(o8[2], o8[3]),
                              bf2(o8[4], o8[5]), bf2(o8[6], o8[7]));
        *(uint4*)(g_o + ((size_t)(w * 64 + r) * 256 + h * 32 + d0)) = o4;
    }
}

// ---------------------------------------------------------------------------
// launch
// ---------------------------------------------------------------------------
extern "C" void kernel_launch(void* const* d_in, const int* in_sizes, int n_in,
                              void* d_out, int out_size)
{
    const float* x0   = (const float*)d_in[0];
    const float* x1   = (const float*)d_in[1];
    const float* g1_0 = (const float*)d_in[2];
    const float* b1_0 = (const float*)d_in[3];
    const float* g1_1 = (const float*)d_in[4];
    const float* b1_1 = (const float*)d_in[5];
    const float* Wq   = (const float*)d_in[6];
    const float* bq   = (const float*)d_in[7];
    const float* Wkv  = (const float*)d_in[8];
    const float* bkv  = (const float*)d_in[9];
    const float* rpb  = (const float*)d_in[10];
    const float* Wp   = (const float*)d_in[11];
    const float* bp   = (const float*)d_in[12];
    const float* g2   = (const float*)d_in[13];
    const float* b2   = (const float*)d_in[14];
    const float* Wfc1 = (const float*)d_in[15];
    const float* bfc1 = (const float*)d_in[16];
    const float* Wfc2 = (const float*)d_in[17];
    const float* bfc2 = (const float*)d_in[18];
    float* out = (float*)d_out;

    // 0) weights -> bf16 scratch
    cvt_w_k<<<768, 256>>>(Wq, Wkv, Wp, Wfc1, Wfc2);

    // 1) LN(x0), LN(x1) + shift + window partition -> g_x0w (0), g_x1w (1)
    ln_win_k<<<16384, 256>>>(x0, x1, g1_0, b1_0, g1_1, b1_1);

    // 2) Q = (x1w @ Wq^T + bq) * scale -> g_q (2, fp32)
    gemm_tc<EPI_SCALE, false><<<dim3(2, 512), 256>>>(1, WOFF_Q, bq, -1, nullptr,
                                                     2, nullptr, 256, 256, SCALE_Q);
    // 3) KV = x0w @ Wkv^T + bkv -> g_kv (3, fp32)
    gemm_tc<EPI_BIAS, false><<<dim3(4, 512), 256>>>(0, WOFF_KV, bkv, -1, nullptr,
                                                    3, nullptr, 512, 256, 1.0f);
    // 4) attention -> g_o (bf16)
    attn_k<<<dim3(8, 1024), 256>>>(rpb);

    // 5) x = x1 + scatter(attn_out @ Wp^T + bp) -> g_x (5, fp32)
    gemm_tc<EPI_SCATTER, false><<<dim3(2, 512), 256>>>(4, WOFF_P, bp, -1, x1,
                                                       5, nullptr, 256, 256, 1.0f);
    // 6) xn = LN2(x) -> g_xn (bf16)
    ln2_k<<<8192, 256>>>(g2, b2);

    // 7) h = gelu(xn @ Wfc1^T + bfc1) -> g_h (bf16)
    gemm_tc<EPI_GELU, true><<<dim3(8, 512), 256>>>(6, WOFF_FC1, bfc1, -1, nullptr,
                                                   -1, nullptr, 1024, 256, 1.0f);
    // 8) out = x + h @ Wfc2^T + bfc2 -> d_out (fp32)
    gemm_tc<EPI_RESID, false><<<dim3(2, 512), 256>>>(7, WOFF_FC2, bfc2, 5, nullptr,
                                                     -1, out, 256, 1024, 1.0f);
}

// round 14
// speedup vs baseline: 3.8157x; 1.0550x over previous
#include <cuda_runtime.h>
#include <cuda_bf16.h>
#include <math.h>
#include <stdint.h>

// ---------------------------------------------------------------------------
// Problem constants
//   B=16, H=W=64, DIM=256, HEADS=8, DHEAD=32, WS=8, SHIFT=4
//   N=64 tokens/window, NW=64 windows/image, NTOK = 65536 tokens
// ---------------------------------------------------------------------------
#define NTOK 65536
#define DIMC 256
#define SCALE_Q 0.17677669529663687f   // 32^-0.5

// ---------------------------------------------------------------------------
// Scratch (device globals — no allocations allowed)
// ---------------------------------------------------------------------------
__device__ __nv_bfloat16 g_x0w[(size_t)NTOK * DIMC];   // LN(x0) windowed
__device__ __nv_bfloat16 g_x1w[(size_t)NTOK * DIMC];   // LN(x1) windowed
__device__ float         g_q  [(size_t)NTOK * DIMC];   // scaled Q (fp32, attn)
__device__ float         g_kv [(size_t)NTOK * 2 * DIMC]; // [K|V] (fp32, attn)
__device__ __nv_bfloat16 g_o  [(size_t)NTOK * DIMC];   // attn out (feeds proj)
__device__ float         g_x  [(size_t)NTOK * DIMC];   // x = shortcut + attn
__device__ __nv_bfloat16 g_xn [(size_t)NTOK * DIMC];   // LN2(x) (feeds FC1)
__device__ __nv_bfloat16 g_h  [(size_t)NTOK * 1024];   // gelu(fc1) (feeds FC2)
__device__ __nv_bfloat16 g_wb [786432];                // bf16 weights

#define WOFF_Q   0
#define WOFF_KV  65536
#define WOFF_P   196608
#define WOFF_FC1 262144
#define WOFF_FC2 524288

__device__ __forceinline__ const __nv_bfloat16* abuf(int id) {
    switch (id) {
        case 0: return g_x0w;
        case 1: return g_x1w;
        case 4: return g_o;
        case 6: return g_xn;
        default: return g_h;
    }
}
__device__ __forceinline__ float* cbuf(int id) {
    switch (id) {
        case 2: return g_q;
        case 3: return g_kv;
        default: return g_x;
    }
}

// windowed row index (w*64+t) -> flat token index (b*4096 + h*64 + w)
__device__ __forceinline__ int win_to_flat(int m) {
    int w  = m >> 6, t = m & 63;
    int b  = w >> 6, wi = w & 63;
    int hs = ((wi >> 3) << 3) + (t >> 3);
    int ws = ((wi & 7) << 3) + (t & 7);
    int hh = (hs + 4) & 63;
    int ww = (ws + 4) & 63;
    return (b << 12) + (hh << 6) + ww;
}

__device__ __forceinline__ uint32_t bf2(float lo, float hi) {
    __nv_bfloat162 h = __floats2bfloat162_rn(lo, hi);
    return *(uint32_t*)&h;
}

__device__ __forceinline__ void mma_bf16(float c[4], const uint32_t a[4],
                                         uint32_t b0, uint32_t b1) {
    asm volatile(
        "mma.sync.aligned.m16n8k16.row.col.f32.bf16.bf16.f32 "
        "{%0,%1,%2,%3}, {%4,%5,%6,%7}, {%8,%9}, {%0,%1,%2,%3};\n"
        : "+f"(c[0]), "+f"(c[1]), "+f"(c[2]), "+f"(c[3])
        : "r"(a[0]), "r"(a[1]), "r"(a[2]), "r"(a[3]), "r"(b0), "r"(b1));
}

#define CP16(dst, src) \
    asm volatile("cp.async.ca.shared.global [%0], [%1], 16;" :: "r"(dst), "l"(src))

#define LDSM4(r0, r1, r2, r3, addr) \
    asm volatile("ldmatrix.sync.aligned.m8n8.x4.shared.b16 {%0,%1,%2,%3}, [%4];" \
        : "=r"(r0), "=r"(r1), "=r"(r2), "=r"(r3) : "r"(addr))

// ---------------------------------------------------------------------------
// One-shot: weights fp32 -> bf16 into g_wb.
// ---------------------------------------------------------------------------
__global__ __launch_bounds__(256) void cvt_w_k(
    const float* __restrict__ Wq, const float* __restrict__ Wkv,
    const float* __restrict__ Wp, const float* __restrict__ Wfc1,
    const float* __restrict__ Wfc2)
{
    int i4 = blockIdx.x * 256 + threadIdx.x;
    const float* src; int off4;
    if      (i4 < 16384)  { src = Wq;   off4 = 0; }
    else if (i4 < 49152)  { src = Wkv;  off4 = 16384; }
    else if (i4 < 65536)  { src = Wp;   off4 = 49152; }
    else if (i4 < 131072) { src = Wfc1; off4 = 65536; }
    else                  { src = Wfc2; off4 = 131072; }
    float4 v = ((const float4*)src)[i4 - off4];
    ((uint2*)g_wb)[i4] = make_uint2(bf2(v.x, v.y), bf2(v.z, v.w));
}

// ---------------------------------------------------------------------------
// LN(x0), LN(x1) + roll + window partition.  One warp per token. bf16 out.
// ---------------------------------------------------------------------------
__global__ __launch_bounds__(256) void ln_win_k(
    const float* __restrict__ x0, const float* __restrict__ x1,
    const float* __restrict__ g0, const float* __restrict__ b0,
    const float* __restrict__ g1, const float* __restrict__ b1)
{
    int warp = blockIdx.x * 8 + (threadIdx.x >> 5);
    int lane = threadIdx.x & 31;
    int which = warp >> 16;
    int tok   = warp & (NTOK - 1);
    int flat  = win_to_flat(tok);

    const float* src = which ? x1 : x0;
    const float* gg  = which ? g1 : g0;
    const float* bb  = which ? b1 : b0;
    __nv_bfloat16* dst = which ? g_x1w : g_x0w;

    const float4* p = (const float4*)(src + (size_t)flat * DIMC);
    float4 u = p[lane * 2], v = p[lane * 2 + 1];

    float s = u.x + u.y + u.z + u.w + v.x + v.y + v.z + v.w;
    float q = u.x*u.x + u.y*u.y + u.z*u.z + u.w*u.w
            + v.x*v.x + v.y*v.y + v.z*v.z + v.w*v.w;
    #pragma unroll
    for (int o = 16; o; o >>= 1) {
        s += __shfl_xor_sync(0xffffffffu, s, o);
        q += __shfl_xor_sync(0xffffffffu, q, o);
    }
    float mean = s * (1.0f / 256.0f);
    float var  = q * (1.0f / 256.0f) - mean * mean;
    float rstd = rsqrtf(var + 1e-5f);

    const float4* gp = (const float4*)gg;
    const float4* bp = (const float4*)bb;
    float4 gu = gp[lane * 2], gv = gp[lane * 2 + 1];
    float4 bu = bp[lane * 2], bv = bp[lane * 2 + 1];

    uint4 o4;
    o4.x = bf2((u.x - mean) * rstd * gu.x + bu.x, (u.y - mean) * rstd * gu.y + bu.y);
    o4.y = bf2((u.z - mean) * rstd * gu.z + bu.z, (u.w - mean) * rstd * gu.w + bu.w);
    o4.z = bf2((v.x - mean) * rstd * gv.x + bv.x, (v.y - mean) * rstd * gv.y + bv.y);
    o4.w = bf2((v.z - mean) * rstd * gv.z + bv.z, (v.w - mean) * rstd * gv.w + bv.w);
    ((uint4*)(dst + (size_t)tok * DIMC))[lane] = o4;
}

// ---------------------------------------------------------------------------
// LN2 of g_x -> g_xn (token order), bf16 out
// ---------------------------------------------------------------------------
__global__ __launch_bounds__(256) void ln2_k(
    const float* __restrict__ gg, const float* __restrict__ bb)
{
    int warp = blockIdx.x * 8 + (threadIdx.x >> 5);
    int lane = threadIdx.x & 31;

    const float4* p = (const float4*)(g_x + (size_t)warp * DIMC);
    float4 u = p[lane * 2], v = p[lane * 2 + 1];

    float s = u.x + u.y + u.z + u.w + v.x + v.y + v.z + v.w;
    float q = u.x*u.x + u.y*u.y + u.z*u.z + u.w*u.w
            + v.x*v.x + v.y*v.y + v.z*v.z + v.w*v.w;
    #pragma unroll
    for (int o = 16; o; o >>= 1) {
        s += __shfl_xor_sync(0xffffffffu, s, o);
        q += __shfl_xor_sync(0xffffffffu, q, o);
    }
    float mean = s * (1.0f / 256.0f);
    float var  = q * (1.0f / 256.0f) - mean * mean;
    float rstd = rsqrtf(var + 1e-5f);

    const float4* gp = (const float4*)gg;
    const float4* bp = (const float4*)bb;
    float4 gu = gp[lane * 2], gv = gp[lane * 2 + 1];
    float4 bu = bp[lane * 2], bv = bp[lane * 2 + 1];

    uint4 o4;
    o4.x = bf2((u.x - mean) * rstd * gu.x + bu.x, (u.y - mean) * rstd * gu.y + bu.y);
    o4.y = bf2((u.z - mean) * rstd * gu.z + bu.z, (u.w - mean) * rstd * gu.w + bu.w);
    o4.z = bf2((v.x - mean) * rstd * gv.x + bv.x, (v.y - mean) * rstd * gv.y + bv.y);
    o4.w = bf2((v.z - mean) * rstd * gv.z + bv.z, (v.w - mean) * rstd * gv.w + bv.w);
    ((uint4*)(g_xn + (size_t)warp * DIMC))[lane] = o4;
}

// ---------------------------------------------------------------------------
// bf16 tensor-core GEMM (cp.async double-buffered, LDSM fragment feed):
//   C[m,n] = sum_k A[m,k] * W[n,k]  (+epilogue)
// Block 128x128x32, 8 warps (4M x 2N), warp 32x64, mma m16n8k16.
// Smem u32 rows pitch 20 (80 B): LDSM 8-row groups hit all 32 banks. 40 KiB.
// Per k-step: 2 A-LDSM.x4 + 4 B-LDSM.x4 feed 16 mmas.
// ---------------------------------------------------------------------------
#define EPI_SCALE   0
#define EPI_BIAS    1
#define EPI_GELU    2
#define EPI_SCATTER 3
#define EPI_RESID   4

template<int EPI, bool OUTBF>
__global__ __launch_bounds__(256) void gemm_tc(
    int a_id, int w_off, const float* __restrict__ bias,
    int r_id, const float* __restrict__ r_ext,
    int c_id, float* __restrict__ c_ext,
    int N, int K, float scale)
{
    __shared__ __align__(16) uint32_t As[2][128][20];   // u32 = bf16x2
    __shared__ __align__(16) uint32_t Bs[2][128][20];

    const __nv_bfloat16* A  = abuf(a_id);
    const __nv_bfloat16* Wm = g_wb + w_off;
    float* C = nullptr;
    if (!OUTBF) C = (c_id >= 0) ? cbuf(c_id) : c_ext;
    const float* R = nullptr;
    if (EPI == EPI_SCATTER || EPI == EPI_RESID)
        R = (r_id >= 0) ? cbuf(r_id) : r_ext;

    int tid  = threadIdx.x;
    int lane = tid & 31;
    int wid  = tid >> 5;
    int wm   = wid & 3;
    int wn   = wid >> 2;
    int m0 = blockIdx.y * 128, n0 = blockIdx.x * 128;

    int lr  = tid >> 2;          // 0..63
    int lc  = (tid & 3) * 4;     // u32 col 0,4,8,12

    uint32_t ab  = (uint32_t)__cvta_generic_to_shared(&As[0][0][0]);
    uint32_t bb_ = (uint32_t)__cvta_generic_to_shared(&Bs[0][0][0]);

    // cp.async destinations
    uint32_t dA0[2], dA1[2], dB0[2], dB1[2];
    #pragma unroll
    for (int b = 0; b < 2; b++) {
        dA0[b] = ab  + ((b * 128 + lr) * 20 + lc) * 4;
        dA1[b] = ab  + ((b * 128 + lr + 64) * 20 + lc) * 4;
        dB0[b] = bb_ + ((b * 128 + lr) * 20 + lc) * 4;
        dB1[b] = bb_ + ((b * 128 + lr + 64) * 20 + lc) * 4;
    }
    const __nv_bfloat16* Ap0 = A  + (size_t)(m0 + lr) * K + lc * 2;
    const __nv_bfloat16* Ap1 = Ap0 + (size_t)64 * K;
    const __nv_bfloat16* Wp0 = Wm + (size_t)(n0 + lr) * K + lc * 2;
    const __nv_bfloat16* Wp1 = Wp0 + (size_t)64 * K;

    // ldmatrix source addresses (group = lane>>3: bit0 -> +8 rows, bit1 -> +4 u32 cols)
    int grp = lane >> 3, rr8 = lane & 7;
    uint32_t aL0 = ab  + (((uint32_t)(wm * 32 + (grp & 1) * 8 + rr8) * 20
                          + (uint32_t)((grp >> 1) * 4)) << 2);
    uint32_t bL0 = bb_ + (((uint32_t)(wn * 64 + (grp & 1) * 8 + rr8) * 20
                          + (uint32_t)((grp >> 1) * 4)) << 2);
    // strides (bytes): mt/pair +16 rows = 1280; ks +8 u32 = 32; buffer +128 rows = 10240

    float acc[2][8][4];
    #pragma unroll
    for (int a = 0; a < 2; a++)
        #pragma unroll
        for (int b = 0; b < 8; b++)
            #pragma unroll
            for (int c = 0; c < 4; c++) acc[a][b][c] = 0.0f;

    int ntile = K >> 5;
    CP16(dA0[0], Ap0);  CP16(dA1[0], Ap1);
    CP16(dB0[0], Wp0);  CP16(dB1[0], Wp1);
    asm volatile("cp.async.commit_group;");

    for (int t = 0; t < ntile; t++) {
        int cur = t & 1;
        if (t + 1 < ntile) {
            int kt = (t + 1) << 5;
            int nb = cur ^ 1;
            CP16(dA0[nb], Ap0 + kt);  CP16(dA1[nb], Ap1 + kt);
            CP16(dB0[nb], Wp0 + kt);  CP16(dB1[nb], Wp1 + kt);
            asm volatile("cp.async.commit_group;");
            asm volatile("cp.async.wait_group 1;");
        } else {
            asm volatile("cp.async.wait_group 0;");
        }
        __syncthreads();

        uint32_t aB = aL0 + cur * 10240;
        uint32_t bB = bL0 + cur * 10240;
        #pragma unroll
        for (int ks = 0; ks < 2; ks++) {
            uint32_t af0[4], af1[4];
            LDSM4(af0[0], af0[1], af0[2], af0[3], aB + ks * 32);
            LDSM4(af1[0], af1[1], af1[2], af1[3], aB + 1280 + ks * 32);
            #pragma unroll
            for (int p = 0; p < 4; p++) {
                uint32_t bf[4];
                LDSM4(bf[0], bf[1], bf[2], bf[3], bB + p * 1280 + ks * 32);
                mma_bf16(acc[0][2 * p],     af0, bf[0], bf[2]);
                mma_bf16(acc[1][2 * p],     af1, bf[0], bf[2]);
                mma_bf16(acc[0][2 * p + 1], af0, bf[1], bf[3]);
                mma_bf16(acc[1][2 * p + 1], af1, bf[1], bf[3]);
            }
        }
        __syncthreads();
    }

    #pragma unroll
    for (int mt = 0; mt < 2; mt++) {
        #pragma unroll
        for (int half = 0; half < 2; half++) {
            int row = m0 + wm * 32 + mt * 16 + (lane >> 2) + half * 8;
            size_t crow;
            if (EPI == EPI_SCATTER) crow = (size_t)win_to_flat(row) * N;
            else                    crow = (size_t)row * N;
            #pragma unroll
            for (int nt = 0; nt < 8; nt++) {
                int col = n0 + wn * 64 + nt * 8 + (lane & 3) * 2;
                float v0 = acc[mt][nt][half * 2 + 0] + bias[col];
                float v1 = acc[mt][nt][half * 2 + 1] + bias[col + 1];
                if (EPI == EPI_SCALE) { v0 *= scale; v1 *= scale; }
                if (EPI == EPI_GELU) {
                    v0 = 0.5f * v0 * (1.0f + erff(v0 * 0.70710678118654752f));
                    v1 = 0.5f * v1 * (1.0f + erff(v1 * 0.70710678118654752f));
                }
                if (EPI == EPI_SCATTER || EPI == EPI_RESID) {
                    float2 rr = *(const float2*)&R[crow + col];
                    v0 += rr.x; v1 += rr.y;
                }
                if (OUTBF) {
                    *(uint32_t*)&g_h[crow + col] = bf2(v0, v1);
                } else {
                    *(float2*)&C[crow + col] = make_float2(v0, v1);
                }
            }
        }
    }
}

// ---------------------------------------------------------------------------
// Attention: one block per (head, window). bf16 output (feeds proj GEMM).
// ---------------------------------------------------------------------------
__global__ __launch_bounds__(256) void attn_k(const float* __restrict__ rpb)
{
    __shared__ float Qs[64][33];
    __shared__ float Ks[64][36];
    __shared__ float Vs[64][36];
    __shared__ float S[64][65];
    __shared__ float bias_s[225];
    __shared__ int   lab[64];

    int h = blockIdx.x;
    int w = blockIdx.y;
    int tid = threadIdx.x;

    {
        int t  = tid >> 2;
        int d0 = (tid & 3) << 3;
        const float* qp = g_q + ((size_t)(w * 64 + t) * 256 + h * 32 + d0);
        float4 a = *(const float4*)qp, b = *(const float4*)(qp + 4);
        Qs[t][d0 + 0] = a.x; Qs[t][d0 + 1] = a.y; Qs[t][d0 + 2] = a.z; Qs[t][d0 + 3] = a.w;
        Qs[t][d0 + 4] = b.x; Qs[t][d0 + 5] = b.y; Qs[t][d0 + 6] = b.z; Qs[t][d0 + 7] = b.w;
        const float* kp = g_kv + ((size_t)(w * 64 + t) * 512 + h * 32 + d0);
        float4 ka = *(const float4*)kp, kb = *(const float4*)(kp + 4);
        *(float4*)&Ks[t][d0]     = ka;
        *(float4*)&Ks[t][d0 + 4] = kb;
        const float* vp = kp + 256;
        float4 va = *(const float4*)vp, vb = *(const float4*)(vp + 4);
        *(float4*)&Vs[t][d0]     = va;
        *(float4*)&Vs[t][d0 + 4] = vb;
    }
    if (tid < 225) bias_s[tid] = rpb[tid * 8 + h];
    if (tid < 64) {
        int wi = w & 63, wr = wi >> 3, wc = wi & 7;
        int rr = tid >> 3, cc = tid & 7;
        int lh = (wr < 7) ? 0 : ((rr < 4) ? 1 : 2);
        int lw = (wc < 7) ? 0 : ((cc < 4) ? 1 : 2);
        lab[tid] = lh * 3 + lw;
    }
    __syncthreads();

    {
        int r  = tid & 63;
        int jg = tid >> 6;
        float qreg[32];
        #pragma unroll
        for (int k = 0; k < 32; k++) qreg[k] = Qs[r][k];
        int lr_ = lab[r];
        int ri = r >> 3, ci = r & 7;

        #pragma unroll
        for (int jj = 0; jj < 16; jj++) {
            int j = jg * 16 + jj;
            float s = 0.0f;
            #pragma unroll
            for (int k4 = 0; k4 < 8; k4++) {
                float4 kv = *(const float4*)&Ks[j][k4 * 4];
                s = fmaf(qreg[k4*4+0], kv.x, s);
                s = fmaf(qreg[k4*4+1], kv.y, s);
                s = fmaf(qreg[k4*4+2], kv.z, s);
                s = fmaf(qreg[k4*4+3], kv.w, s);
            }
            int rj = j >> 3, cj = j & 7;
            s += bias_s[(ri - rj + 7) * 15 + (ci - cj + 7)];
            if (lr_ != lab[j]) s -= 100.0f;
            S[r][j] = s;
        }
    }
    __syncthreads();

    {
        int r = tid >> 2;
        int q = tid & 3;
        float m = -1e30f;
        #pragma unroll
        for (int jj = 0; jj < 16; jj++) m = fmaxf(m, S[r][q * 16 + jj]);
        m = fmaxf(m, __shfl_xor_sync(0xffffffffu, m, 1));
        m = fmaxf(m, __shfl_xor_sync(0xffffffffu, m, 2));
        float sum = 0.0f;
        float e[16];
        #pragma unroll
        for (int jj = 0; jj < 16; jj++) {
            e[jj] = expf(S[r][q * 16 + jj] - m);
            sum += e[jj];
        }
        sum += __shfl_xor_sync(0xffffffffu, sum, 1);
        sum += __shfl_xor_sync(0xffffffffu, sum, 2);
        float inv = 1.0f / sum;
        #pragma unroll
        for (int jj = 0; jj < 16; jj++) S[r][q * 16 + jj] = e[jj] * inv;
    }
    __syncthreads();

    {
        int r  = tid & 63;
        int dg = tid >> 6;
        int d0 = dg * 8;
        float o8[8] = {0, 0, 0, 0, 0, 0, 0, 0};
        #pragma unroll
        for (int j = 0; j < 64; j++) {
            float p = S[r][j];
            float4 v0 = *(const float4*)&Vs[j][d0];
            float4 v1 = *(const float4*)&Vs[j][d0 + 4];
            o8[0] = fmaf(p, v0.x, o8[0]); o8[1] = fmaf(p, v0.y, o8[1]);
            o8[2] = fmaf(p, v0.z, o8[2]); o8[3] = fmaf(p, v0.w, o8[3]);
            o8[4] = fmaf(p, v1.x, o8[4]); o8[5] = fmaf(p, v1.y, o8[5]);
            o8[6] = fmaf(p, v1.z, o8[6]); o8[7] = fmaf(p, v1.w, o8[7]);
        }
        uint4 o4 = make_uint4(bf2(o8[0], o8[1]), bf2(o8[2], o8[3]),
                              bf2(o8[4], o8[5]), bf2(o8[6], o8[7]));
        *(uint4*)(g_o + ((size_t)(w * 64 + r) * 256 + h * 32 + d0)) = o4;
    }
}

// ---------------------------------------------------------------------------
// launch
// ---------------------------------------------------------------------------
extern "C" void kernel_launch(void* const* d_in, const int* in_sizes, int n_in,
                              void* d_out, int out_size)
{
    const float* x0   = (const float*)d_in[0];
    const float* x1   = (const float*)d_in[1];
    const float* g1_0 = (const float*)d_in[2];
    const float* b1_0 = (const float*)d_in[3];
    const float* g1_1 = (const float*)d_in[4];
    const float* b1_1 = (const float*)d_in[5];
    const float* Wq   = (const float*)d_in[6];
    const float* bq   = (const float*)d_in[7];
    const float* Wkv  = (const float*)d_in[8];
    const float* bkv  = (const float*)d_in[9];
    const float* rpb  = (const float*)d_in[10];
    const float* Wp   = (const float*)d_in[11];
    const float* bp   = (const float*)d_in[12];
    const float* g2   = (const float*)d_in[13];
    const float* b2   = (const float*)d_in[14];
    const float* Wfc1 = (const float*)d_in[15];
    const float* bfc1 = (const float*)d_in[16];
    const float* Wfc2 = (const float*)d_in[17];
    const float* bfc2 = (const float*)d_in[18];
    float* out = (float*)d_out;

    // 0) weights -> bf16 scratch
    cvt_w_k<<<768, 256>>>(Wq, Wkv, Wp, Wfc1, Wfc2);

    // 1) LN(x0), LN(x1) + shift + window partition -> g_x0w (0), g_x1w (1)
    ln_win_k<<<16384, 256>>>(x0, x1, g1_0, b1_0, g1_1, b1_1);

    // 2) Q = (x1w @ Wq^T + bq) * scale -> g_q (fp32)
    gemm_tc<EPI_SCALE, false><<<dim3(2, 512), 256>>>(1, WOFF_Q, bq, -1, nullptr,
                                                     2, nullptr, 256, 256, SCALE_Q);
    // 3) KV = x0w @ Wkv^T + bkv -> g_kv (fp32)
    gemm_tc<EPI_BIAS, false><<<dim3(4, 512), 256>>>(0, WOFF_KV, bkv, -1, nullptr,
                                                    3, nullptr, 512, 256, 1.0f);
    // 4) attention -> g_o (bf16)
    attn_k<<<dim3(8, 1024), 256>>>(rpb);

    // 5) x = x1 + scatter(attn_out @ Wp^T + bp) -> g_x (fp32)
    gemm_tc<EPI_SCATTER, false><<<dim3(2, 512), 256>>>(4, WOFF_P, bp, -1, x1,
                                                       5, nullptr, 256, 256, 1.0f);
    // 6) xn = LN2(x) -> g_xn (bf16)
    ln2_k<<<8192, 256>>>(g2, b2);

    // 7) h = gelu(xn @ Wfc1^T + bfc1) -> g_h (bf16)
    gemm_tc<EPI_GELU, true><<<dim3(8, 512), 256>>>(6, WOFF_FC1, bfc1, -1, nullptr,
                                                   -1, nullptr, 1024, 256, 1.0f);
    // 8) out = x + h @ Wfc2^T + bfc2 -> d_out (fp32)
    gemm_tc<EPI_RESID, false><<<dim3(2, 512), 256>>>(7, WOFF_FC2, bfc2, 5, nullptr,
                                                     -1, out, 256, 1024, 1.0f);
}

// round 16
// speedup vs baseline: 4.6926x; 1.2298x over previous
#include <cuda_runtime.h>
#include <cuda_bf16.h>
#include <math.h>
#include <stdint.h>

// ---------------------------------------------------------------------------
// Problem constants: B=16, H=W=64, DIM=256, HEADS=8, DHEAD=32, WS=8, SHIFT=4
// N=64 tok/window, NW=64, NTOK=65536, 1024 windows total
// ---------------------------------------------------------------------------
#define NTOK 65536
#define DIMC 256
#define SCALE_Q 0.17677669529663687f

// ---------------------------------------------------------------------------
// Scratch (device globals — no allocations allowed)
// ---------------------------------------------------------------------------
__device__ __nv_bfloat16 g_x0w[(size_t)NTOK * DIMC];   // LN(x0) windowed
__device__ __nv_bfloat16 g_x1w[(size_t)NTOK * DIMC];   // LN(x1) windowed
__device__ __nv_bfloat16 g_qb [(size_t)NTOK * DIMC];   // scaled Q, bf16
__device__ __nv_bfloat16 g_kb [(size_t)NTOK * DIMC];   // K, bf16
__device__ __nv_bfloat16 g_vt [(size_t)NTOK * DIMC];   // V transposed: ((w*8+h)*32+d)*64 + t
__device__ __nv_bfloat16 g_o  [(size_t)NTOK * DIMC];   // attn out (windowed)
__device__ float         g_x  [(size_t)NTOK * DIMC];   // x = shortcut + attn
__device__ __nv_bfloat16 g_xn [(size_t)NTOK * DIMC];   // LN2(x)
__device__ __nv_bfloat16 g_h  [(size_t)NTOK * 1024];   // gelu(fc1)
__device__ __nv_bfloat16 g_wb [786432];                // bf16 weights

#define WOFF_Q   0
#define WOFF_KV  65536
#define WOFF_P   196608
#define WOFF_FC1 262144
#define WOFF_FC2 524288

__device__ __forceinline__ const __nv_bfloat16* abuf(int id) {
    switch (id) {
        case 0: return g_x0w;
        case 1: return g_x1w;
        case 4: return g_o;
        case 6: return g_xn;
        default: return g_h;
    }
}
__device__ __forceinline__ float* cbuf(int id) {
    return g_x;   // only fp32 scratch dest
}
__device__ __forceinline__ __nv_bfloat16* bbuf(int id) {
    switch (id) {
        case 2: return g_qb;
        default: return g_h;
    }
}

// windowed row index (w*64+t) -> flat token index
__device__ __forceinline__ int win_to_flat(int m) {
    int w  = m >> 6, t = m & 63;
    int b  = w >> 6, wi = w & 63;
    int hs = ((wi >> 3) << 3) + (t >> 3);
    int ws = ((wi & 7) << 3) + (t & 7);
    int hh = (hs + 4) & 63;
    int ww = (ws + 4) & 63;
    return (b << 12) + (hh << 6) + ww;
}

__device__ __forceinline__ uint32_t bf2(float lo, float hi) {
    __nv_bfloat162 h = __floats2bfloat162_rn(lo, hi);
    return *(uint32_t*)&h;
}

__device__ __forceinline__ void mma_bf16(float c[4], const uint32_t a[4],
                                         uint32_t b0, uint32_t b1) {
    asm volatile(
        "mma.sync.aligned.m16n8k16.row.col.f32.bf16.bf16.f32 "
        "{%0,%1,%2,%3}, {%4,%5,%6,%7}, {%8,%9}, {%0,%1,%2,%3};\n"
        : "+f"(c[0]), "+f"(c[1]), "+f"(c[2]), "+f"(c[3])
        : "r"(a[0]), "r"(a[1]), "r"(a[2]), "r"(a[3]), "r"(b0), "r"(b1));
}

#define CP16(dst, src) \
    asm volatile("cp.async.ca.shared.global [%0], [%1], 16;" :: "r"(dst), "l"(src))

#define LDSM4(r0, r1, r2, r3, addr) \
    asm volatile("ldmatrix.sync.aligned.m8n8.x4.shared.b16 {%0,%1,%2,%3}, [%4];" \
        : "=r"(r0), "=r"(r1), "=r"(r2), "=r"(r3) : "r"(addr))

// ---------------------------------------------------------------------------
// One-shot: weights fp32 -> bf16
// ---------------------------------------------------------------------------
__global__ __launch_bounds__(256) void cvt_w_k(
    const float* __restrict__ Wq, const float* __restrict__ Wkv,
    const float* __restrict__ Wp, const float* __restrict__ Wfc1,
    const float* __restrict__ Wfc2)
{
    int i4 = blockIdx.x * 256 + threadIdx.x;
    const float* src; int off4;
    if      (i4 < 16384)  { src = Wq;   off4 = 0; }
    else if (i4 < 49152)  { src = Wkv;  off4 = 16384; }
    else if (i4 < 65536)  { src = Wp;   off4 = 49152; }
    else if (i4 < 131072) { src = Wfc1; off4 = 65536; }
    else                  { src = Wfc2; off4 = 131072; }
    float4 v = ((const float4*)src)[i4 - off4];
    ((uint2*)g_wb)[i4] = make_uint2(bf2(v.x, v.y), bf2(v.z, v.w));
}

// ---------------------------------------------------------------------------
// LN(x0), LN(x1) + roll + window partition. One warp/token. bf16 out.
// ---------------------------------------------------------------------------
__global__ __launch_bounds__(256) void ln_win_k(
    const float* __restrict__ x0, const float* __restrict__ x1,
    const float* __restrict__ g0, const float* __restrict__ b0,
    const float* __restrict__ g1, const float* __restrict__ b1)
{
    int warp = blockIdx.x * 8 + (threadIdx.x >> 5);
    int lane = threadIdx.x & 31;
    int which = warp >> 16;
    int tok   = warp & (NTOK - 1);
    int flat  = win_to_flat(tok);

    const float* src = which ? x1 : x0;
    const float* gg  = which ? g1 : g0;
    const float* bb  = which ? b1 : b0;
    __nv_bfloat16* dst = which ? g_x1w : g_x0w;

    const float4* p = (const float4*)(src + (size_t)flat * DIMC);
    float4 u = p[lane * 2], v = p[lane * 2 + 1];

    float s = u.x + u.y + u.z + u.w + v.x + v.y + v.z + v.w;
    float q = u.x*u.x + u.y*u.y + u.z*u.z + u.w*u.w
            + v.x*v.x + v.y*v.y + v.z*v.z + v.w*v.w;
    #pragma unroll
    for (int o = 16; o; o >>= 1) {
        s += __shfl_xor_sync(0xffffffffu, s, o);
        q += __shfl_xor_sync(0xffffffffu, q, o);
    }
    float mean = s * (1.0f / 256.0f);
    float var  = q * (1.0f / 256.0f) - mean * mean;
    float rstd = rsqrtf(var + 1e-5f);

    const float4* gp = (const float4*)gg;
    const float4* bp = (const float4*)bb;
    float4 gu = gp[lane * 2], gv = gp[lane * 2 + 1];
    float4 bu = bp[lane * 2], bv = bp[lane * 2 + 1];

    uint4 o4;
    o4.x = bf2((u.x - mean) * rstd * gu.x + bu.x, (u.y - mean) * rstd * gu.y + bu.y);
    o4.y = bf2((u.z - mean) * rstd * gu.z + bu.z, (u.w - mean) * rstd * gu.w + bu.w);
    o4.z = bf2((v.x - mean) * rstd * gv.x + bv.x, (v.y - mean) * rstd * gv.y + bv.y);
    o4.w = bf2((v.z - mean) * rstd * gv.z + bv.z, (v.w - mean) * rstd * gv.w + bv.w);
    ((uint4*)(dst + (size_t)tok * DIMC))[lane] = o4;
}

// ---------------------------------------------------------------------------
// LN2 of g_x -> g_xn, bf16 out
// ---------------------------------------------------------------------------
__global__ __launch_bounds__(256) void ln2_k(
    const float* __restrict__ gg, const float* __restrict__ bb)
{
    int warp = blockIdx.x * 8 + (threadIdx.x >> 5);
    int lane = threadIdx.x & 31;

    const float4* p = (const float4*)(g_x + (size_t)warp * DIMC);
    float4 u = p[lane * 2], v = p[lane * 2 + 1];

    float s = u.x + u.y + u.z + u.w + v.x + v.y + v.z + v.w;
    float q = u.x*u.x + u.y*u.y + u.z*u.z + u.w*u.w
            + v.x*v.x + v.y*v.y + v.z*v.z + v.w*v.w;
    #pragma unroll
    for (int o = 16; o; o >>= 1) {
        s += __shfl_xor_sync(0xffffffffu, s, o);
        q += __shfl_xor_sync(0xffffffffu, q, o);
    }
    float mean = s * (1.0f / 256.0f);
    float var  = q * (1.0f / 256.0f) - mean * mean;
    float rstd = rsqrtf(var + 1e-5f);

    const float4* gp = (const float4*)gg;
    const float4* bp = (const float4*)bb;
    float4 gu = gp[lane * 2], gv = gp[lane * 2 + 1];
    float4 bu = bp[lane * 2], bv = bp[lane * 2 + 1];

    uint4 o4;
    o4.x = bf2((u.x - mean) * rstd * gu.x + bu.x, (u.y - mean) * rstd * gu.y + bu.y);
    o4.y = bf2((u.z - mean) * rstd * gu.z + bu.z, (u.w - mean) * rstd * gu.w + bu.w);
    o4.z = bf2((v.x - mean) * rstd * gv.x + bv.x, (v.y - mean) * rstd * gv.y + bv.y);
    o4.w = bf2((v.z - mean) * rstd * gv.z + bv.z, (v.w - mean) * rstd * gv.w + bv.w);
    ((uint4*)(g_xn + (size_t)warp * DIMC))[lane] = o4;
}

// ---------------------------------------------------------------------------
// bf16 tensor-core GEMM (cp.async double-buffered, LDSM fragment feed).
// Epilogues: SCALE->bf16 g_qb, KV->g_kb + transposed g_vt, SCATTER->fp32 g_x,
// GELU->bf16 g_h, RESID->fp32 out.
// ---------------------------------------------------------------------------
#define EPI_SCALE   0
#define EPI_KV      1
#define EPI_GELU    2
#define EPI_SCATTER 3
#define EPI_RESID   4

template<int EPI, bool OUTBF>
__global__ __launch_bounds__(256) void gemm_tc(
    int a_id, int w_off, const float* __restrict__ bias,
    int r_id, const float* __restrict__ r_ext,
    int c_id, float* __restrict__ c_ext,
    int N, int K, float scale)
{
    __shared__ __align__(16) uint32_t As[2][128][20];
    __shared__ __align__(16) uint32_t Bs[2][128][20];

    const __nv_bfloat16* A  = abuf(a_id);
    const __nv_bfloat16* Wm = g_wb + w_off;
    float* C = nullptr;
    if (!OUTBF && EPI != EPI_KV) C = (c_id >= 0) ? cbuf(c_id) : c_ext;
    const float* R = nullptr;
    if (EPI == EPI_SCATTER || EPI == EPI_RESID)
        R = (r_id >= 0) ? cbuf(r_id) : r_ext;

    int tid  = threadIdx.x;
    int lane = tid & 31;
    int wid  = tid >> 5;
    int wm   = wid & 3;
    int wn   = wid >> 2;
    int m0 = blockIdx.y * 128, n0 = blockIdx.x * 128;

    int lr  = tid >> 2;
    int lc  = (tid & 3) * 4;

    uint32_t ab  = (uint32_t)__cvta_generic_to_shared(&As[0][0][0]);
    uint32_t bb_ = (uint32_t)__cvta_generic_to_shared(&Bs[0][0][0]);

    uint32_t dA0[2], dA1[2], dB0[2], dB1[2];
    #pragma unroll
    for (int b = 0; b < 2; b++) {
        dA0[b] = ab  + ((b * 128 + lr) * 20 + lc) * 4;
        dA1[b] = ab  + ((b * 128 + lr + 64) * 20 + lc) * 4;
        dB0[b] = bb_ + ((b * 128 + lr) * 20 + lc) * 4;
        dB1[b] = bb_ + ((b * 128 + lr + 64) * 20 + lc) * 4;
    }
    const __nv_bfloat16* Ap0 = A  + (size_t)(m0 + lr) * K + lc * 2;
    const __nv_bfloat16* Ap1 = Ap0 + (size_t)64 * K;
    const __nv_bfloat16* Wp0 = Wm + (size_t)(n0 + lr) * K + lc * 2;
    const __nv_bfloat16* Wp1 = Wp0 + (size_t)64 * K;

    int grp = lane >> 3, rr8 = lane & 7;
    uint32_t aL0 = ab  + (((uint32_t)(wm * 32 + (grp & 1) * 8 + rr8) * 20
                          + (uint32_t)((grp >> 1) * 4)) << 2);
    uint32_t bL0 = bb_ + (((uint32_t)(wn * 64 + (grp & 1) * 8 + rr8) * 20
                          + (uint32_t)((grp >> 1) * 4)) << 2);

    float acc[2][8][4];
    #pragma unroll
    for (int a = 0; a < 2; a++)
        #pragma unroll
        for (int b = 0; b < 8; b++)
            #pragma unroll
            for (int c = 0; c < 4; c++) acc[a][b][c] = 0.0f;

    int ntile = K >> 5;
    CP16(dA0[0], Ap0);  CP16(dA1[0], Ap1);
    CP16(dB0[0], Wp0);  CP16(dB1[0], Wp1);
    asm volatile("cp.async.commit_group;");

    for (int t = 0; t < ntile; t++) {
        int cur = t & 1;
        if (t + 1 < ntile) {
            int kt = (t + 1) << 5;
            int nb = cur ^ 1;
            CP16(dA0[nb], Ap0 + kt);  CP16(dA1[nb], Ap1 + kt);
            CP16(dB0[nb], Wp0 + kt);  CP16(dB1[nb], Wp1 + kt);
            asm volatile("cp.async.commit_group;");
            asm volatile("cp.async.wait_group 1;");
        } else {
            asm volatile("cp.async.wait_group 0;");
        }
        __syncthreads();

        uint32_t aB = aL0 + cur * 10240;
        uint32_t bB = bL0 + cur * 10240;
        #pragma unroll
        for (int ks = 0; ks < 2; ks++) {
            uint32_t af0[4], af1[4];
            LDSM4(af0[0], af0[1], af0[2], af0[3], aB + ks * 32);
            LDSM4(af1[0], af1[1], af1[2], af1[3], aB + 1280 + ks * 32);
            #pragma unroll
            for (int p = 0; p < 4; p++) {
                uint32_t bf[4];
                LDSM4(bf[0], bf[1], bf[2], bf[3], bB + p * 1280 + ks * 32);
                mma_bf16(acc[0][2 * p],     af0, bf[0], bf[2]);
                mma_bf16(acc[1][2 * p],     af1, bf[0], bf[2]);
                mma_bf16(acc[0][2 * p + 1], af0, bf[1], bf[3]);
                mma_bf16(acc[1][2 * p + 1], af1, bf[1], bf[3]);
            }
        }
        __syncthreads();
    }

    #pragma unroll
    for (int mt = 0; mt < 2; mt++) {
        #pragma unroll
        for (int half = 0; half < 2; half++) {
            int row = m0 + wm * 32 + mt * 16 + (lane >> 2) + half * 8;
            size_t crow = 0;
            if (EPI == EPI_SCATTER)      crow = (size_t)win_to_flat(row) * N;
            else if (EPI != EPI_KV)      crow = (size_t)row * N;
            #pragma unroll
            for (int nt = 0; nt < 8; nt++) {
                int col = n0 + wn * 64 + nt * 8 + (lane & 3) * 2;
                float v0 = acc[mt][nt][half * 2 + 0] + bias[col];
                float v1 = acc[mt][nt][half * 2 + 1] + bias[col + 1];
                if (EPI == EPI_SCALE) { v0 *= scale; v1 *= scale; }
                if (EPI == EPI_GELU) {
                    v0 = 0.5f * v0 * (1.0f + erff(v0 * 0.70710678118654752f));
                    v1 = 0.5f * v1 * (1.0f + erff(v1 * 0.70710678118654752f));
                }
                if (EPI == EPI_SCATTER || EPI == EPI_RESID) {
                    float2 rr = *(const float2*)&R[crow + col];
                    v0 += rr.x; v1 += rr.y;
                }
                if (EPI == EPI_KV) {
                    if (col < 256) {
                        *(uint32_t*)&g_kb[(size_t)row * 256 + col] = bf2(v0, v1);
                    } else {
                        int hd = col - 256;
                        size_t base = (((size_t)(row >> 6) * 8 + (hd >> 5)) * 32
                                       + (hd & 31)) * 64 + (row & 63);
                        g_vt[base]      = __float2bfloat16(v0);
                        g_vt[base + 64] = __float2bfloat16(v1);
                    }
                } else if (OUTBF) {
                    *(uint32_t*)&bbuf(c_id)[crow + col] = bf2(v0, v1);
                } else {
                    *(float2*)&C[crow + col] = make_float2(v0, v1);
                }
            }
        }
    }
}

// ---------------------------------------------------------------------------
// Tensor-core attention: block = window (1024 blocks), warp = head.
// S = Q K^T via mma (A from Qs, B from Ks rows), softmax on C-frags,
// P repacked in-register as A-frags, O = P V via mma (B from pre-transposed Vt).
// Smem: Qs[64][264]b, Ks[64][264]b, Vt[256][72]b, bias[8][228]f  = 111744 B.
// ---------------------------------------------------------------------------
#define AT_QOFF 0
#define AT_KOFF 33792
#define AT_VOFF 67584
#define AT_BOFF 104448
#define AT_SMEM 111744

__global__ __launch_bounds__(256) void attn_mma_k(const float* __restrict__ rpb)
{
    extern __shared__ __align__(16) char sm[];
    uint32_t u;
    asm("{ .reg .u64 t; cvta.to.shared.u64 t, %1; cvt.u32.u64 %0, t; }"
        : "=r"(u) : "l"(sm));

    int tid = threadIdx.x, lane = tid & 31, h = tid >> 5;
    int w = blockIdx.x;

    // ---- stage Q, K (rows=token, pitch 264 bf16) and Vt (rows=h*32+d, pitch 72) ----
    {
        const uint4* qg = (const uint4*)(g_qb + (size_t)w * 64 * 256);
        const uint4* kg = (const uint4*)(g_kb + (size_t)w * 64 * 256);
        const uint4* vg = (const uint4*)(g_vt + (size_t)w * 16384);
        #pragma unroll
        for (int i = 0; i < 8; i++) {
            int c = i * 256 + tid;            // 0..2047
            int row = c >> 5, seg = c & 31;
            *(uint4*)(sm + AT_QOFF + row * 528 + seg * 16) = qg[c];
            *(uint4*)(sm + AT_KOFF + row * 528 + seg * 16) = kg[c];
            int vr = c >> 3, vs = c & 7;
            *(uint4*)(sm + AT_VOFF + vr * 144 + vs * 16) = vg[c];
        }
        float* bsm = (float*)(sm + AT_BOFF);
        for (int k = tid; k < 1800; k += 256) {
            int hh = k / 225, idx = k - hh * 225;
            bsm[hh * 228 + idx] = rpb[idx * 8 + hh];
        }
    }
    __syncthreads();

    // ---- per-warp (head h) ----
    int lr8 = lane & 7, lb = (lane >> 3) & 1, lk = lane >> 4;
    uint32_t rowoff = lr8 + lb * 8;
    uint32_t qb = u + AT_QOFF + rowoff * 528 + h * 64 + lk * 16;
    uint32_t kb = u + AT_KOFF + rowoff * 528 + h * 64 + lk * 16;
    uint32_t vb = u + AT_VOFF + (h * 32 + rowoff) * 144 + lk * 16;
    const float* bs = (const float*)(sm + AT_BOFF) + h * 228;

    int r0 = lane >> 2, c2 = (lane & 3) * 2;
    int wi = w & 63;
    int fR = ((wi >> 3) == 7), fC = ((wi & 7) == 7);

    #pragma unroll 1
    for (int rc = 0; rc < 4; rc++) {
        // ---- S = Q K^T ----
        float S[8][4];
        #pragma unroll
        for (int n = 0; n < 8; n++)
            #pragma unroll
            for (int c = 0; c < 4; c++) S[n][c] = 0.0f;

        #pragma unroll
        for (int kt = 0; kt < 2; kt++) {
            uint32_t aq[4];
            LDSM4(aq[0], aq[1], aq[2], aq[3], qb + rc * 8448 + kt * 32);
            #pragma unroll
            for (int p = 0; p < 4; p++) {
                uint32_t bf[4];
                LDSM4(bf[0], bf[1], bf[2], bf[3], kb + p * 8448 + kt * 32);
                mma_bf16(S[2 * p],     aq, bf[0], bf[2]);
                mma_bf16(S[2 * p + 1], aq, bf[1], bf[3]);
            }
        }

        // ---- bias + mask + softmax (rows i0 = rc*16+r0 and i1 = i0+8) ----
        int i0 = rc * 16 + r0, i1 = i0 + 8;
        int ri0 = i0 >> 3, ci0 = i0 & 7, ri1 = i1 >> 3, ci1 = i1 & 7;
        int li0 = (fR ? ((ri0 < 4) ? 3 : 6) : 0) + (fC ? ((ci0 < 4) ? 1 : 2) : 0);
        int li1 = (fR ? ((ri1 < 4) ? 3 : 6) : 0) + (fC ? ((ci1 < 4) ? 1 : 2) : 0);

        float mx0 = -1e30f, mx1 = -1e30f;
        #pragma unroll
        for (int nt = 0; nt < 8; nt++) {
            #pragma unroll
            for (int cc = 0; cc < 2; cc++) {
                int j = nt * 8 + c2 + cc;
                int rj = j >> 3, cj = j & 7;
                int lj = (fR ? ((rj < 4) ? 3 : 6) : 0) + (fC ? ((cj < 4) ? 1 : 2) : 0);
                float v0 = S[nt][cc]     + bs[(ri0 - rj + 7) * 15 + (ci0 - cj + 7)];
                float v1 = S[nt][cc + 2] + bs[(ri1 - rj + 7) * 15 + (ci1 - cj + 7)];
                if (lj != li0) v0 -= 100.0f;
                if (lj != li1) v1 -= 100.0f;
                S[nt][cc] = v0; S[nt][cc + 2] = v1;
                mx0 = fmaxf(mx0, v0); mx1 = fmaxf(mx1, v1);
            }
        }
        mx0 = fmaxf(mx0, __shfl_xor_sync(0xffffffffu, mx0, 1));
        mx0 = fmaxf(mx0, __shfl_xor_sync(0xffffffffu, mx0, 2));
        mx1 = fmaxf(mx1, __shfl_xor_sync(0xffffffffu, mx1, 1));
        mx1 = fmaxf(mx1, __shfl_xor_sync(0xffffffffu, mx1, 2));

        float sum0 = 0.0f, sum1 = 0.0f;
        #pragma unroll
        for (int nt = 0; nt < 8; nt++) {
            #pragma unroll
            for (int cc = 0; cc < 2; cc++) {
                float e0 = __expf(S[nt][cc] - mx0);
                float e1 = __expf(S[nt][cc + 2] - mx1);
                S[nt][cc] = e0; S[nt][cc + 2] = e1;
                sum0 += e0; sum1 += e1;
            }
        }
        sum0 += __shfl_xor_sync(0xffffffffu, sum0, 1);
        sum0 += __shfl_xor_sync(0xffffffffu, sum0, 2);
        sum1 += __shfl_xor_sync(0xffffffffu, sum1, 1);
        sum1 += __shfl_xor_sync(0xffffffffu, sum1, 2);
        float inv0 = __fdividef(1.0f, sum0);
        float inv1 = __fdividef(1.0f, sum1);
        #pragma unroll
        for (int nt = 0; nt < 8; nt++) {
            S[nt][0] *= inv0; S[nt][1] *= inv0;
            S[nt][2] *= inv1; S[nt][3] *= inv1;
        }

        // ---- repack P (S C-frags) as A-frags; O = P V ----
        float O[4][4];
        #pragma unroll
        for (int n = 0; n < 4; n++)
            #pragma unroll
            for (int c = 0; c < 4; c++) O[n][c] = 0.0f;

        #pragma unroll
        for (int kt = 0; kt < 4; kt++) {
            uint32_t aP[4];
            aP[0] = bf2(S[2 * kt][0],     S[2 * kt][1]);
            aP[1] = bf2(S[2 * kt][2],     S[2 * kt][3]);
            aP[2] = bf2(S[2 * kt + 1][0], S[2 * kt + 1][1]);
            aP[3] = bf2(S[2 * kt + 1][2], S[2 * kt + 1][3]);
            #pragma unroll
            for (int dp = 0; dp < 2; dp++) {
                uint32_t bf[4];
                LDSM4(bf[0], bf[1], bf[2], bf[3], vb + dp * 2304 + kt * 32);
                mma_bf16(O[2 * dp],     aP, bf[0], bf[2]);
                mma_bf16(O[2 * dp + 1], aP, bf[1], bf[3]);
            }
        }

        // ---- store O chunk (bf16, windowed layout) ----
        #pragma unroll
        for (int nt = 0; nt < 4; nt++) {
            int col = h * 32 + nt * 8 + c2;
            *(uint32_t*)&g_o[(size_t)(w * 64 + i0) * 256 + col] = bf2(O[nt][0], O[nt][1]);
            *(uint32_t*)&g_o[(size_t)(w * 64 + i1) * 256 + col] = bf2(O[nt][2], O[nt][3]);
        }
    }
}

// ---------------------------------------------------------------------------
// launch
// ---------------------------------------------------------------------------
extern "C" void kernel_launch(void* const* d_in, const int* in_sizes, int n_in,
                              void* d_out, int out_size)
{
    const float* x0   = (const float*)d_in[0];
    const float* x1   = (const float*)d_in[1];
    const float* g1_0 = (const float*)d_in[2];
    const float* b1_0 = (const float*)d_in[3];
    const float* g1_1 = (const float*)d_in[4];
    const float* b1_1 = (const float*)d_in[5];
    const float* Wq   = (const float*)d_in[6];
    const float* bq   = (const float*)d_in[7];
    const float* Wkv  = (const float*)d_in[8];
    const float* bkv  = (const float*)d_in[9];
    const float* rpb  = (const float*)d_in[10];
    const float* Wp   = (const float*)d_in[11];
    const float* bp   = (const float*)d_in[12];
    const float* g2   = (const float*)d_in[13];
    const float* b2   = (const float*)d_in[14];
    const float* Wfc1 = (const float*)d_in[15];
    const float* bfc1 = (const float*)d_in[16];
    const float* Wfc2 = (const float*)d_in[17];
    const float* bfc2 = (const float*)d_in[18];
    float* out = (float*)d_out;

    cudaFuncSetAttribute(attn_mma_k, cudaFuncAttributeMaxDynamicSharedMemorySize, AT_SMEM);

    // 0) weights -> bf16 scratch
    cvt_w_k<<<768, 256>>>(Wq, Wkv, Wp, Wfc1, Wfc2);

    // 1) LN(x0), LN(x1) + shift + window partition
    ln_win_k<<<16384, 256>>>(x0, x1, g1_0, b1_0, g1_1, b1_1);

    // 2) Q = (x1w @ Wq^T + bq) * scale -> g_qb (bf16)
    gemm_tc<EPI_SCALE, true><<<dim3(2, 512), 256>>>(1, WOFF_Q, bq, -1, nullptr,
                                                    2, nullptr, 256, 256, SCALE_Q);
    // 3) K -> g_kb, V -> g_vt (transposed per window/head)
    gemm_tc<EPI_KV, false><<<dim3(4, 512), 256>>>(0, WOFF_KV, bkv, -1, nullptr,
                                                  -1, nullptr, 512, 256, 1.0f);
    // 4) attention (tensor-core) -> g_o (bf16)
    attn_mma_k<<<1024, 256, AT_SMEM>>>(rpb);

    // 5) x = x1 + scatter(attn_out @ Wp^T + bp) -> g_x (fp32)
    gemm_tc<EPI_SCATTER, false><<<dim3(2, 512), 256>>>(4, WOFF_P, bp, -1, x1,
                                                       5, nullptr, 256, 256, 1.0f);
    // 6) xn = LN2(x) -> g_xn (bf16)
    ln2_k<<<8192, 256>>>(g2, b2);

    // 7) h = gelu(xn @ Wfc1^T + bfc1) -> g_h (bf16)
    gemm_tc<EPI_GELU, true><<<dim3(8, 512), 256>>>(6, WOFF_FC1, bfc1, -1, nullptr,
                                                   7, nullptr, 1024, 256, 1.0f);
    // 8) out = x + h @ Wfc2^T + bfc2 -> d_out (fp32)
    gemm_tc<EPI_RESID, false><<<dim3(2, 512), 256>>>(7, WOFF_FC2, bfc2, 5, nullptr,
                                                     -1, out, 256, 1024, 1.0f);
}